// round 2
// baseline (speedup 1.0000x reference)
#include <cuda_runtime.h>
#include <cuda_bf16.h>

// Problem constants (fixed-shape problem)
#define MAXN 50176
#define MAXE 800256
#define D128 128

// ---------------- scratch (no allocation allowed; 16B-aligned for vector access) ----------------
__device__ __align__(16) float g_xw[MAXN * 128];   // transposed per node: [cc][h] -> idx cc*4+h
__device__ __align__(16) float g_id[MAXN * 128];   // identity = x@W_proj + b_proj, layout [node][c]
__device__ __align__(16) float g_as[MAXN * 4];
__device__ __align__(16) float g_ad[MAXN * 4];
__device__ int   g_off[MAXN + 1];
__device__ int   g_cur[MAXN];
__device__ int   g_csr[MAXE];
__device__ float g_G[128];           // colsum of gamma*W_gat
__device__ float g_B[128];           // beta @ W_gat

// ---------------- f32x2 helpers ----------------
__device__ __forceinline__ unsigned long long pk2(float a) {
    unsigned long long r;
    asm("mov.b64 %0, {%1, %1};" : "=l"(r) : "f"(a));
    return r;
}
__device__ __forceinline__ void fma2(unsigned long long &d, unsigned long long a, unsigned long long b) {
    asm("fma.rn.f32x2 %0, %1, %2, %0;" : "+l"(d) : "l"(a), "l"(b));
}
__device__ __forceinline__ float2 up2(unsigned long long v) {
    float2 f;
    asm("mov.b64 {%0, %1}, %2;" : "=f"(f.x), "=f"(f.y) : "l"(v));
    return f;
}

// ---------------- prep: G_c = sum_k gamma_k*Wgat[k][c], B_c = sum_k beta_k*Wgat[k][c] ----------------
__global__ void prep_k(const float* __restrict__ gamma, const float* __restrict__ beta,
                       const float* __restrict__ Wgat) {
    int c = threadIdx.x;
    if (c < 128) {
        float G = 0.f, B = 0.f;
        for (int k = 0; k < 128; k++) {
            float w = Wgat[k * 128 + c];
            G += gamma[k] * w;
            B += beta[k] * w;
        }
        g_G[c] = G;
        g_B[c] = B;
    }
}

// ---------------- CSR build ----------------
__global__ void zero_k(int n) {
    int i = blockIdx.x * blockDim.x + threadIdx.x;
    if (i < n) g_cur[i] = 0;
}
__global__ void hist_k(const int* __restrict__ dst, int e) {
    int i = blockIdx.x * blockDim.x + threadIdx.x;
    if (i < e) atomicAdd(&g_cur[dst[i]], 1);
}
__global__ void scan_k(int n) {
    __shared__ int wsum[32];
    __shared__ int s_carry;
    int tid = threadIdx.x, lane = tid & 31, wid = tid >> 5;
    if (tid == 0) s_carry = 0;
    __syncthreads();
    for (int base = 0; base < n; base += 1024) {
        int i = base + tid;
        int v = (i < n) ? g_cur[i] : 0;
        int incl = v;
        #pragma unroll
        for (int o = 1; o < 32; o <<= 1) {
            int t = __shfl_up_sync(0xFFFFFFFFu, incl, o);
            if (lane >= o) incl += t;
        }
        if (lane == 31) wsum[wid] = incl;
        __syncthreads();
        if (wid == 0) {
            int wv = wsum[lane];
            int wincl = wv;
            #pragma unroll
            for (int o = 1; o < 32; o <<= 1) {
                int t = __shfl_up_sync(0xFFFFFFFFu, wincl, o);
                if (lane >= o) wincl += t;
            }
            wsum[lane] = wincl - wv;  // exclusive warp offset
        }
        __syncthreads();
        int carry = s_carry;
        int inc_total = carry + wsum[wid] + incl;
        if (i < n) {
            g_off[i + 1] = inc_total;
            g_cur[i] = inc_total - v;  // start offset
        }
        __syncthreads();
        if (tid == 1023) s_carry = inc_total;
        __syncthreads();
    }
    if (threadIdx.x == 0) g_off[0] = 0;
}
__global__ void scat_k(const int* __restrict__ src, const int* __restrict__ dst, int e) {
    int i = blockIdx.x * blockDim.x + threadIdx.x;
    if (i < e) {
        int p = atomicAdd(&g_cur[dst[i]], 1);
        g_csr[p] = src[i];
    }
}

// ---------------- fused node kernel: LN + dual GEMM + attention dots ----------------
// Tile: 64 nodes x 256 output cols (128 xw + 128 identity), K=128, 256 threads.
// Thread (ty=tid/32, tx=tid%32): rows ty*8..+7, cols tx*4..+3 (xw) and 128+tx*4..+3 (id).
#define TM 64
#define XT_PITCH 68   // multiple of 4 => every k*XT_PITCH float4-aligned
// smem floats: Bs 32768, xT 128*68=8704, smu 64, srstd 64, satt 256, sG 128, sB 128, sbp 128
#define NODE_SMEM_FLOATS (32768 + 128 * XT_PITCH + 64 + 64 + 256 + 128 + 128 + 128)
#define NODE_SMEM_BYTES (NODE_SMEM_FLOATS * 4)

__global__ void __launch_bounds__(256, 1) node_k(
    const float* __restrict__ x, const float* __restrict__ gamma,
    const float* __restrict__ Wgat, const float* __restrict__ Wproj,
    const float* __restrict__ att_src, const float* __restrict__ att_dst,
    const float* __restrict__ bproj, int n)
{
    extern __shared__ float sm[];
    float* Bs    = sm;                       // [128][256]
    float* xT    = Bs + 32768;               // [128][XT_PITCH]
    float* smu   = xT + 128 * XT_PITCH;      // [64]
    float* srstd = smu + TM;                 // [64]
    float* satt  = srstd + TM;               // [256]: att_src 0..127, att_dst 128..255
    float* sG    = satt + 256;               // [128]
    float* sB    = sG + 128;                 // [128]
    float* sbp   = sB + 128;                 // [128]

    int tid = threadIdx.x;
    int i0 = blockIdx.x * TM;

    // Load B = [gamma*Wgat | Wproj] into smem: Bs[k][c] = Bs[k*256+c]
    for (int t = tid; t < 32768; t += 256) {
        int k = t >> 8, c = t & 255;
        float v;
        if (c < 128) v = gamma[k] * Wgat[k * 128 + c];
        else         v = Wproj[k * 128 + (c - 128)];
        Bs[t] = v;
    }
    if (tid < 128) {
        satt[tid]       = att_src[tid];
        satt[128 + tid] = att_dst[tid];
        sG[tid] = g_G[tid];
        sB[tid] = g_B[tid];
        sbp[tid] = bproj[tid];
    }

    // Load x tile rows + LayerNorm stats + transpose into xT[k][r]
    int wid = tid >> 5, lane = tid & 31;
    for (int rr = 0; rr < 8; rr++) {
        int r = wid * 8 + rr;
        int node = i0 + r;
        float4 v = make_float4(0.f, 0.f, 0.f, 0.f);
        if (node < n) v = *(const float4*)&x[(long)node * 128 + lane * 4];
        float s = v.x + v.y + v.z + v.w;
        float q = v.x * v.x + v.y * v.y + v.z * v.z + v.w * v.w;
        #pragma unroll
        for (int o = 16; o > 0; o >>= 1) {
            s += __shfl_xor_sync(0xFFFFFFFFu, s, o);
            q += __shfl_xor_sync(0xFFFFFFFFu, q, o);
        }
        float mu = s * (1.f / 128.f);
        float var = q * (1.f / 128.f) - mu * mu;
        float rstd = rsqrtf(var + 1e-5f);
        if (lane == 0) { smu[r] = mu; srstd[r] = rstd; }
        int kbase = lane * 4;
        xT[(kbase + 0) * XT_PITCH + r] = v.x;
        xT[(kbase + 1) * XT_PITCH + r] = v.y;
        xT[(kbase + 2) * XT_PITCH + r] = v.z;
        xT[(kbase + 3) * XT_PITCH + r] = v.w;
    }
    __syncthreads();

    int ty = tid >> 5;  // warp id = row group
    int tx = tid & 31;  // col group

    unsigned long long acc[32];
    #pragma unroll
    for (int t = 0; t < 32; t++) acc[t] = 0ull;

    const float* xbase = &xT[ty * 8];
    const float* bbase = &Bs[tx * 4];

    #pragma unroll 4
    for (int k = 0; k < 128; k++) {
        float4 a0 = *(const float4*)&xbase[k * XT_PITCH];
        float4 a1 = *(const float4*)&xbase[k * XT_PITCH + 4];
        ulonglong2 B0 = *(const ulonglong2*)&bbase[k * 256];        // xw cols pair
        ulonglong2 B1 = *(const ulonglong2*)&bbase[k * 256 + 128];  // id cols pair
        float af[8] = {a0.x, a0.y, a0.z, a0.w, a1.x, a1.y, a1.z, a1.w};
        #pragma unroll
        for (int i = 0; i < 8; i++) {
            unsigned long long pa = pk2(af[i]);
            fma2(acc[i * 4 + 0], pa, B0.x);
            fma2(acc[i * 4 + 1], pa, B0.y);
            fma2(acc[i * 4 + 2], pa, B1.x);
            fma2(acc[i * 4 + 3], pa, B1.y);
        }
    }

    // Epilogue
    int h = tx >> 3;          // head for this thread's xw cols
    int ccb = (tx & 7) * 4;   // channel base within head
    #pragma unroll
    for (int i = 0; i < 8; i++) {
        int r = ty * 8 + i;
        int node = i0 + r;
        if (node >= n) continue;  // uniform across warp
        float mu = smu[r], rs = srstd[r];
        float2 v0 = up2(acc[i * 4 + 0]);
        float2 v1 = up2(acc[i * 4 + 1]);
        float2 w0 = up2(acc[i * 4 + 2]);
        float2 w1 = up2(acc[i * 4 + 3]);
        float xwv[4] = {v0.x, v0.y, v1.x, v1.y};
        float idv[4] = {w0.x, w0.y, w1.x, w1.y};
        float ps = 0.f, pd = 0.f;
        float outxw[4];
        #pragma unroll
        for (int j = 0; j < 4; j++) {
            int c = tx * 4 + j;
            float val = rs * (xwv[j] - mu * sG[c]) + sB[c];
            outxw[j] = val;
            ps += val * satt[c];
            pd += val * satt[128 + c];
        }
        // write xw transposed: [node][cc][h] -> node*128 + cc*4 + h
        long base = (long)node * 128;
        #pragma unroll
        for (int j = 0; j < 4; j++)
            g_xw[base + (ccb + j) * 4 + h] = outxw[j];
        // identity [node][c]
        float4 iv = make_float4(idv[0] + sbp[tx * 4 + 0], idv[1] + sbp[tx * 4 + 1],
                                idv[2] + sbp[tx * 4 + 2], idv[3] + sbp[tx * 4 + 3]);
        *(float4*)&g_id[base + tx * 4] = iv;
        // reduce attention partials across 8 lanes of this head group
        #pragma unroll
        for (int o = 1; o < 8; o <<= 1) {
            ps += __shfl_xor_sync(0xFFFFFFFFu, ps, o);
            pd += __shfl_xor_sync(0xFFFFFFFFu, pd, o);
        }
        if ((tx & 7) == 0) {
            g_as[node * 4 + h] = ps;
            g_ad[node * 4 + h] = pd;
        }
    }
}

// ---------------- gather: online softmax + aggregate + epilogue ----------------
__device__ __forceinline__ float lrelu(float z) { return z > 0.f ? z : 0.2f * z; }

__device__ __forceinline__ void proc(float as_h, float ad_h, float &m, float &d, float &a, float xv) {
    float z = lrelu(as_h + ad_h);
    if (z <= m) {
        float p = __expf(z - m);
        d += p;
        a = fmaf(p, xv, a);
    } else {
        float sc = __expf(m - z);
        d = fmaf(d, sc, 1.f);
        a = fmaf(a, sc, xv);
        m = z;
    }
}

__global__ void __launch_bounds__(256) gather_k(const float* __restrict__ bias,
                                                float* __restrict__ out, int n)
{
    int gw = (blockIdx.x * 256 + threadIdx.x) >> 5;
    int lane = threadIdx.x & 31;
    if (gw >= n) return;
    int i = gw;
    float4 ad  = *(const float4*)&g_ad[i * 4];
    float4 asi = *(const float4*)&g_as[i * 4];
    long myb = (long)i * 128;
    float4 xv = *(const float4*)&g_xw[myb + lane * 4];

    // self loop
    float m0 = lrelu(asi.x + ad.x), m1 = lrelu(asi.y + ad.y);
    float m2 = lrelu(asi.z + ad.z), m3 = lrelu(asi.w + ad.w);
    float d0 = 1.f, d1 = 1.f, d2 = 1.f, d3 = 1.f;
    float a0 = xv.x, a1 = xv.y, a2 = xv.z, a3 = xv.w;

    int beg = g_off[i], end = g_off[i + 1];
    for (int j = beg; j < end; j++) {
        int s = __ldg(&g_csr[j]);
        float4 a4 = *(const float4*)&g_as[s * 4];
        float4 x4 = *(const float4*)&g_xw[(long)s * 128 + lane * 4];
        proc(a4.x, ad.x, m0, d0, a0, x4.x);
        proc(a4.y, ad.y, m1, d1, a1, x4.y);
        proc(a4.z, ad.z, m2, d2, a2, x4.z);
        proc(a4.w, ad.w, m3, d3, a3, x4.w);
    }

    float r0 = a0 / (d0 + 1e-16f);
    float r1 = a1 / (d1 + 1e-16f);
    float r2 = a2 / (d2 + 1e-16f);
    float r3 = a3 / (d3 + 1e-16f);

    // out[node][h*32+lane] = relu(identity + agg + bias)
    long ob = myb + lane;
    out[ob +  0] = fmaxf(g_id[ob +  0] + r0 + __ldg(&bias[lane +  0]), 0.f);
    out[ob + 32] = fmaxf(g_id[ob + 32] + r1 + __ldg(&bias[lane + 32]), 0.f);
    out[ob + 64] = fmaxf(g_id[ob + 64] + r2 + __ldg(&bias[lane + 64]), 0.f);
    out[ob + 96] = fmaxf(g_id[ob + 96] + r3 + __ldg(&bias[lane + 96]), 0.f);
}

// ---------------- launch ----------------
extern "C" void kernel_launch(void* const* d_in, const int* in_sizes, int n_in,
                              void* d_out, int out_size)
{
    const float* x        = (const float*)d_in[0];
    const int*   ei       = (const int*)d_in[1];
    const float* gamma    = (const float*)d_in[2];
    const float* beta     = (const float*)d_in[3];
    const float* Wgat     = (const float*)d_in[4];
    const float* att_src  = (const float*)d_in[5];
    const float* att_dst  = (const float*)d_in[6];
    const float* bias_gat = (const float*)d_in[7];
    const float* Wproj    = (const float*)d_in[8];
    const float* bproj    = (const float*)d_in[9];

    int n = in_sizes[0] / 128;
    int e = in_sizes[1] / 2;
    const int* src = ei;
    const int* dst = ei + e;

    cudaFuncSetAttribute(node_k, cudaFuncAttributeMaxDynamicSharedMemorySize, NODE_SMEM_BYTES);

    prep_k<<<1, 128>>>(gamma, beta, Wgat);
    zero_k<<<(n + 255) / 256, 256>>>(n);
    hist_k<<<(e + 255) / 256, 256>>>(dst, e);
    scan_k<<<1, 1024>>>(n);
    scat_k<<<(e + 255) / 256, 256>>>(src, dst, e);
    node_k<<<(n + TM - 1) / TM, 256, NODE_SMEM_BYTES>>>(x, gamma, Wgat, Wproj,
                                                        att_src, att_dst, bproj, n);
    gather_k<<<(n + 7) / 8, 256>>>(bias_gat, (float*)d_out, n);
}

// round 3
// speedup vs baseline: 1.2047x; 1.2047x over previous
#include <cuda_runtime.h>
#include <cuda_bf16.h>

// Problem constants (fixed-shape problem)
#define MAXN 50176
#define MAXE 800256

// ---------------- scratch (no allocation allowed; 16B-aligned for vector access) ----------------
__device__ __align__(16) float g_xw[MAXN * 128];   // xw per node, layout [node][cc*4+h]
__device__ __align__(16) float g_id[MAXN * 128];   // identity = x@W_proj + b_proj, layout [node][c]
__device__ __align__(16) float g_as[MAXN * 4];
__device__ __align__(16) float g_ad[MAXN * 4];
__device__ __align__(16) int   g_cur[MAXN];
__device__ int   g_off[MAXN + 1];
__device__ int   g_csr[MAXE];
__device__ int   g_bsum[64];
__device__ float g_G[128];           // colsum of gamma*W_gat
__device__ float g_B[128];           // beta @ W_gat

// ---------------- f32x2 helpers ----------------
__device__ __forceinline__ unsigned long long pk2(float a) {
    unsigned long long r;
    asm("mov.b64 %0, {%1, %1};" : "=l"(r) : "f"(a));
    return r;
}
__device__ __forceinline__ void fma2(unsigned long long &d, unsigned long long a, unsigned long long b) {
    asm("fma.rn.f32x2 %0, %1, %2, %0;" : "+l"(d) : "l"(a), "l"(b));
}
__device__ __forceinline__ float2 up2(unsigned long long v) {
    float2 f;
    asm("mov.b64 {%0, %1}, %2;" : "=f"(f.x), "=f"(f.y) : "l"(v));
    return f;
}

// ---------------- prep: G_c = sum_k gamma_k*Wgat[k][c], B_c = sum_k beta_k*Wgat[k][c] ----------------
__global__ void prep_k(const float* __restrict__ gamma, const float* __restrict__ beta,
                       const float* __restrict__ Wgat) {
    int c = threadIdx.x;
    if (c < 128) {
        float G = 0.f, B = 0.f;
        for (int k = 0; k < 128; k++) {
            float w = Wgat[k * 128 + c];
            G += gamma[k] * w;
            B += beta[k] * w;
        }
        g_G[c] = G;
        g_B[c] = B;
    }
}

// ---------------- CSR build ----------------
__global__ void hist_k(const int* __restrict__ dst, int e) {
    int i = blockIdx.x * blockDim.x + threadIdx.x;
    if (i < e) atomicAdd(&g_cur[dst[i]], 1);
}

// Phase 1: per-1024-chunk sums. grid = nb, block = 256 (4 elems/thread, int4).
#define SCB 1024
__global__ void bsum_k(int n) {
    __shared__ int wsum[8];
    int b = blockIdx.x, tid = threadIdx.x, lane = tid & 31, wid = tid >> 5;
    int base = b * SCB + tid * 4;
    int4 v = make_int4(0, 0, 0, 0);
    if (base + 3 < n)      v = *(const int4*)&g_cur[base];
    else {
        if (base     < n) v.x = g_cur[base];
        if (base + 1 < n) v.y = g_cur[base + 1];
        if (base + 2 < n) v.z = g_cur[base + 2];
    }
    int s = v.x + v.y + v.z + v.w;
    #pragma unroll
    for (int o = 16; o > 0; o >>= 1) s += __shfl_xor_sync(0xFFFFFFFFu, s, o);
    if (lane == 0) wsum[wid] = s;
    __syncthreads();
    if (wid == 0 && lane < 8) {
        int t = wsum[lane];
        #pragma unroll
        for (int o = 4; o > 0; o >>= 1) t += __shfl_xor_sync(0xFFu, t, o);
        if (lane == 0) g_bsum[b] = t;
    }
}

// Phase 2: exclusive scan of <=64 block sums, 1 block of 64 threads.
__global__ void bscan_k(int nb) {
    __shared__ int w0tot;
    int tid = threadIdx.x, lane = tid & 31, wid = tid >> 5;
    int v = (tid < nb) ? g_bsum[tid] : 0;
    int inc = v;
    #pragma unroll
    for (int o = 1; o < 32; o <<= 1) {
        int t = __shfl_up_sync(0xFFFFFFFFu, inc, o);
        if (lane >= o) inc += t;
    }
    if (wid == 0 && lane == 31) w0tot = inc;
    __syncthreads();
    int ex = inc - v + (wid == 1 ? w0tot : 0);
    if (tid < nb) g_bsum[tid] = ex;
}

// Phase 3: block-local scan + global fixup. Writes g_off[i+1] (inclusive) and
// g_cur[i] (exclusive start, reused as running cursor by scat_k).
__global__ void scanfin_k(int n) {
    __shared__ int wsum[8];
    int b = blockIdx.x, tid = threadIdx.x, lane = tid & 31, wid = tid >> 5;
    int base = b * SCB + tid * 4;
    int4 v = make_int4(0, 0, 0, 0);
    if (base + 3 < n)      v = *(const int4*)&g_cur[base];
    else {
        if (base     < n) v.x = g_cur[base];
        if (base + 1 < n) v.y = g_cur[base + 1];
        if (base + 2 < n) v.z = g_cur[base + 2];
    }
    int tsum = v.x + v.y + v.z + v.w;
    int inc = tsum;
    #pragma unroll
    for (int o = 1; o < 32; o <<= 1) {
        int t = __shfl_up_sync(0xFFFFFFFFu, inc, o);
        if (lane >= o) inc += t;
    }
    if (lane == 31) wsum[wid] = inc;
    __syncthreads();
    if (wid == 0 && lane < 8) {
        int wv = wsum[lane];
        int wi = wv;
        #pragma unroll
        for (int o = 1; o < 8; o <<= 1) {
            int t = __shfl_up_sync(0xFFu, wi, o);
            if (lane >= o) wi += t;
        }
        wsum[lane] = wi - wv;  // exclusive warp offset
    }
    __syncthreads();
    int e0 = inc - tsum + wsum[wid] + g_bsum[b];
    int e1 = e0 + v.x, e2 = e1 + v.y, e3 = e2 + v.z, e4 = e3 + v.w;
    if (base     < n) { g_cur[base]     = e0; g_off[base + 1] = e1; }
    if (base + 1 < n) { g_cur[base + 1] = e1; g_off[base + 2] = e2; }
    if (base + 2 < n) { g_cur[base + 2] = e2; g_off[base + 3] = e3; }
    if (base + 3 < n) { g_cur[base + 3] = e3; g_off[base + 4] = e4; }
    if (b == 0 && tid == 0) g_off[0] = 0;
}

__global__ void scat_k(const int* __restrict__ src, const int* __restrict__ dst, int e) {
    int i = blockIdx.x * blockDim.x + threadIdx.x;
    if (i < e) {
        int p = atomicAdd(&g_cur[dst[i]], 1);
        g_csr[p] = src[i];
    }
}

// ---------------- fused node kernel: LN + dual GEMM + attention dots ----------------
#define TM 64
#define XT_PITCH 68   // multiple of 4 => every k*XT_PITCH float4-aligned
#define NODE_SMEM_FLOATS (32768 + 128 * XT_PITCH + 64 + 64 + 256 + 128 + 128 + 128)
#define NODE_SMEM_BYTES (NODE_SMEM_FLOATS * 4)

__global__ void __launch_bounds__(256, 1) node_k(
    const float* __restrict__ x, const float* __restrict__ gamma,
    const float* __restrict__ Wgat, const float* __restrict__ Wproj,
    const float* __restrict__ att_src, const float* __restrict__ att_dst,
    const float* __restrict__ bproj, int n)
{
    extern __shared__ float sm[];
    float* Bs    = sm;                       // [128][256]
    float* xT    = Bs + 32768;               // [128][XT_PITCH]
    float* smu   = xT + 128 * XT_PITCH;      // [64]
    float* srstd = smu + TM;                 // [64]
    float* satt  = srstd + TM;               // [256]
    float* sG    = satt + 256;               // [128]
    float* sB    = sG + 128;                 // [128]
    float* sbp   = sB + 128;                 // [128]

    int tid = threadIdx.x;
    int i0 = blockIdx.x * TM;

    for (int t = tid; t < 32768; t += 256) {
        int k = t >> 8, c = t & 255;
        float v;
        if (c < 128) v = gamma[k] * Wgat[k * 128 + c];
        else         v = Wproj[k * 128 + (c - 128)];
        Bs[t] = v;
    }
    if (tid < 128) {
        satt[tid]       = att_src[tid];
        satt[128 + tid] = att_dst[tid];
        sG[tid] = g_G[tid];
        sB[tid] = g_B[tid];
        sbp[tid] = bproj[tid];
    }

    int wid = tid >> 5, lane = tid & 31;
    for (int rr = 0; rr < 8; rr++) {
        int r = wid * 8 + rr;
        int node = i0 + r;
        float4 v = make_float4(0.f, 0.f, 0.f, 0.f);
        if (node < n) v = *(const float4*)&x[(long)node * 128 + lane * 4];
        float s = v.x + v.y + v.z + v.w;
        float q = v.x * v.x + v.y * v.y + v.z * v.z + v.w * v.w;
        #pragma unroll
        for (int o = 16; o > 0; o >>= 1) {
            s += __shfl_xor_sync(0xFFFFFFFFu, s, o);
            q += __shfl_xor_sync(0xFFFFFFFFu, q, o);
        }
        float mu = s * (1.f / 128.f);
        float var = q * (1.f / 128.f) - mu * mu;
        float rstd = rsqrtf(var + 1e-5f);
        if (lane == 0) { smu[r] = mu; srstd[r] = rstd; }
        int kbase = lane * 4;
        xT[(kbase + 0) * XT_PITCH + r] = v.x;
        xT[(kbase + 1) * XT_PITCH + r] = v.y;
        xT[(kbase + 2) * XT_PITCH + r] = v.z;
        xT[(kbase + 3) * XT_PITCH + r] = v.w;
    }
    __syncthreads();

    int ty = tid >> 5;
    int tx = tid & 31;

    unsigned long long acc[32];
    #pragma unroll
    for (int t = 0; t < 32; t++) acc[t] = 0ull;

    const float* xbase = &xT[ty * 8];
    const float* bbase = &Bs[tx * 4];

    #pragma unroll 4
    for (int k = 0; k < 128; k++) {
        float4 a0 = *(const float4*)&xbase[k * XT_PITCH];
        float4 a1 = *(const float4*)&xbase[k * XT_PITCH + 4];
        ulonglong2 B0 = *(const ulonglong2*)&bbase[k * 256];
        ulonglong2 B1 = *(const ulonglong2*)&bbase[k * 256 + 128];
        float af[8] = {a0.x, a0.y, a0.z, a0.w, a1.x, a1.y, a1.z, a1.w};
        #pragma unroll
        for (int i = 0; i < 8; i++) {
            unsigned long long pa = pk2(af[i]);
            fma2(acc[i * 4 + 0], pa, B0.x);
            fma2(acc[i * 4 + 1], pa, B0.y);
            fma2(acc[i * 4 + 2], pa, B1.x);
            fma2(acc[i * 4 + 3], pa, B1.y);
        }
    }

    int h = tx >> 3;
    int ccb = (tx & 7) * 4;
    #pragma unroll
    for (int i = 0; i < 8; i++) {
        int r = ty * 8 + i;
        int node = i0 + r;
        if (node >= n) continue;
        float mu = smu[r], rs = srstd[r];
        float2 v0 = up2(acc[i * 4 + 0]);
        float2 v1 = up2(acc[i * 4 + 1]);
        float2 w0 = up2(acc[i * 4 + 2]);
        float2 w1 = up2(acc[i * 4 + 3]);
        float xwv[4] = {v0.x, v0.y, v1.x, v1.y};
        float idv[4] = {w0.x, w0.y, w1.x, w1.y};
        float ps = 0.f, pd = 0.f;
        float outxw[4];
        #pragma unroll
        for (int j = 0; j < 4; j++) {
            int c = tx * 4 + j;
            float val = rs * (xwv[j] - mu * sG[c]) + sB[c];
            outxw[j] = val;
            ps += val * satt[c];
            pd += val * satt[128 + c];
        }
        long base = (long)node * 128;
        #pragma unroll
        for (int j = 0; j < 4; j++)
            g_xw[base + (ccb + j) * 4 + h] = outxw[j];
        float4 iv = make_float4(idv[0] + sbp[tx * 4 + 0], idv[1] + sbp[tx * 4 + 1],
                                idv[2] + sbp[tx * 4 + 2], idv[3] + sbp[tx * 4 + 3]);
        *(float4*)&g_id[base + tx * 4] = iv;
        #pragma unroll
        for (int o = 1; o < 8; o <<= 1) {
            ps += __shfl_xor_sync(0xFFFFFFFFu, ps, o);
            pd += __shfl_xor_sync(0xFFFFFFFFu, pd, o);
        }
        if ((tx & 7) == 0) {
            g_as[node * 4 + h] = ps;
            g_ad[node * 4 + h] = pd;
        }
    }
}

// ---------------- gather: two-pass softmax + aggregate + epilogue ----------------
__device__ __forceinline__ float lrelu(float z) { return z > 0.f ? z : 0.2f * z; }

__global__ void __launch_bounds__(256) gather_k(const float* __restrict__ bias,
                                                float* __restrict__ out, int n)
{
    int gw = (blockIdx.x * 256 + threadIdx.x) >> 5;
    int lane = threadIdx.x & 31;
    if (gw >= n) return;
    int i = gw;
    float4 ad  = *(const float4*)&g_ad[i * 4];
    float4 asi = *(const float4*)&g_as[i * 4];
    int beg = g_off[i], end = g_off[i + 1];

    // self-loop scores
    float z0s = lrelu(asi.x + ad.x), z1s = lrelu(asi.y + ad.y);
    float z2s = lrelu(asi.z + ad.z), z3s = lrelu(asi.w + ad.w);

    // ---- pass 1: segment max (lanes parallel over edges) ----
    float m0 = z0s, m1 = z1s, m2 = z2s, m3 = z3s;
    for (int j = beg + lane; j < end; j += 32) {
        int s = __ldg(&g_csr[j]);
        float4 a4 = *(const float4*)&g_as[s * 4];
        m0 = fmaxf(m0, lrelu(a4.x + ad.x));
        m1 = fmaxf(m1, lrelu(a4.y + ad.y));
        m2 = fmaxf(m2, lrelu(a4.z + ad.z));
        m3 = fmaxf(m3, lrelu(a4.w + ad.w));
    }
    #pragma unroll
    for (int o = 16; o > 0; o >>= 1) {
        m0 = fmaxf(m0, __shfl_xor_sync(0xFFFFFFFFu, m0, o));
        m1 = fmaxf(m1, __shfl_xor_sync(0xFFFFFFFFu, m1, o));
        m2 = fmaxf(m2, __shfl_xor_sync(0xFFFFFFFFu, m2, o));
        m3 = fmaxf(m3, __shfl_xor_sync(0xFFFFFFFFu, m3, o));
    }

    // ---- pass 2: branch-free accumulate ----
    long myb = (long)i * 128;
    float4 xv = *(const float4*)&g_xw[myb + lane * 4];
    float p0 = __expf(z0s - m0), p1 = __expf(z1s - m1);
    float p2 = __expf(z2s - m2), p3 = __expf(z3s - m3);
    float d0 = p0, d1 = p1, d2 = p2, d3 = p3;
    float a0 = p0 * xv.x, a1 = p1 * xv.y, a2 = p2 * xv.z, a3 = p3 * xv.w;

    #pragma unroll 2
    for (int j = beg; j < end; j++) {
        int s = __ldg(&g_csr[j]);
        float4 a4 = *(const float4*)&g_as[s * 4];
        float4 x4 = *(const float4*)&g_xw[(long)s * 128 + lane * 4];
        float q0 = __expf(lrelu(a4.x + ad.x) - m0);
        float q1 = __expf(lrelu(a4.y + ad.y) - m1);
        float q2 = __expf(lrelu(a4.z + ad.z) - m2);
        float q3 = __expf(lrelu(a4.w + ad.w) - m3);
        d0 += q0; a0 = fmaf(q0, x4.x, a0);
        d1 += q1; a1 = fmaf(q1, x4.y, a1);
        d2 += q2; a2 = fmaf(q2, x4.z, a2);
        d3 += q3; a3 = fmaf(q3, x4.w, a3);
    }

    float r0 = a0 / (d0 + 1e-16f);
    float r1 = a1 / (d1 + 1e-16f);
    float r2 = a2 / (d2 + 1e-16f);
    float r3 = a3 / (d3 + 1e-16f);

    long ob = myb + lane;
    out[ob +  0] = fmaxf(g_id[ob +  0] + r0 + __ldg(&bias[lane +  0]), 0.f);
    out[ob + 32] = fmaxf(g_id[ob + 32] + r1 + __ldg(&bias[lane + 32]), 0.f);
    out[ob + 64] = fmaxf(g_id[ob + 64] + r2 + __ldg(&bias[lane + 64]), 0.f);
    out[ob + 96] = fmaxf(g_id[ob + 96] + r3 + __ldg(&bias[lane + 96]), 0.f);
}

// ---------------- launch ----------------
extern "C" void kernel_launch(void* const* d_in, const int* in_sizes, int n_in,
                              void* d_out, int out_size)
{
    const float* x        = (const float*)d_in[0];
    const int*   ei       = (const int*)d_in[1];
    const float* gamma    = (const float*)d_in[2];
    const float* beta     = (const float*)d_in[3];
    const float* Wgat     = (const float*)d_in[4];
    const float* att_src  = (const float*)d_in[5];
    const float* att_dst  = (const float*)d_in[6];
    const float* bias_gat = (const float*)d_in[7];
    const float* Wproj    = (const float*)d_in[8];
    const float* bproj    = (const float*)d_in[9];

    int n = in_sizes[0] / 128;
    int e = in_sizes[1] / 2;
    const int* src = ei;
    const int* dst = ei + e;
    int nb = (n + SCB - 1) / SCB;

    void* curp = nullptr;
    cudaGetSymbolAddress(&curp, g_cur);

    cudaFuncSetAttribute(node_k, cudaFuncAttributeMaxDynamicSharedMemorySize, NODE_SMEM_BYTES);

    cudaMemsetAsync(curp, 0, n * sizeof(int));
    hist_k<<<(e + 255) / 256, 256>>>(dst, e);
    bsum_k<<<nb, 256>>>(n);
    bscan_k<<<1, 64>>>(nb);
    scanfin_k<<<nb, 256>>>(n);
    prep_k<<<1, 128>>>(gamma, beta, Wgat);
    scat_k<<<(e + 255) / 256, 256>>>(src, dst, e);
    node_k<<<(n + TM - 1) / TM, 256, NODE_SMEM_BYTES>>>(x, gamma, Wgat, Wproj,
                                                        att_src, att_dst, bproj, n);
    gather_k<<<(n + 7) / 8, 256>>>(bias_gat, (float*)d_out, n);
}

// round 4
// speedup vs baseline: 1.3309x; 1.1047x over previous
#include <cuda_runtime.h>
#include <cuda_bf16.h>

// Problem constants (fixed-shape problem)
#define MAXN 50176
#define MAXE 800256

// ---------------- scratch (no allocation allowed; 16B-aligned for vector access) ----------------
__device__ __align__(16) float g_xw[MAXN * 128];   // xw per node, layout [node][cc*4+h]
__device__ __align__(16) float g_id[MAXN * 128];   // identity = x@W_proj + b_proj, layout [node][c]
__device__ __align__(16) float g_as[MAXN * 4];
__device__ __align__(16) float g_ad[MAXN * 4];
__device__ __align__(16) int   g_cur[MAXN];
__device__ int   g_off[MAXN + 1];
__device__ int   g_csr[MAXE];
__device__ int   g_bsum[64];
__device__ float g_G[128];           // colsum of gamma*W_gat
__device__ float g_B[128];           // beta @ W_gat

// ---------------- f32x2 helpers ----------------
__device__ __forceinline__ unsigned long long pk2(float a) {
    unsigned long long r;
    asm("mov.b64 %0, {%1, %1};" : "=l"(r) : "f"(a));
    return r;
}
__device__ __forceinline__ void fma2(unsigned long long &d, unsigned long long a, unsigned long long b) {
    asm("fma.rn.f32x2 %0, %1, %2, %0;" : "+l"(d) : "l"(a), "l"(b));
}
__device__ __forceinline__ float2 up2(unsigned long long v) {
    float2 f;
    asm("mov.b64 {%0, %1}, %2;" : "=f"(f.x), "=f"(f.y) : "l"(v));
    return f;
}

// ---------------- prep: G_c = sum_k gamma_k*Wgat[k][c], B_c = sum_k beta_k*Wgat[k][c] ----------------
__global__ void prep_k(const float* __restrict__ gamma, const float* __restrict__ beta,
                       const float* __restrict__ Wgat) {
    int c = threadIdx.x;
    if (c < 128) {
        float G = 0.f, B = 0.f;
        for (int k = 0; k < 128; k++) {
            float w = Wgat[k * 128 + c];
            G += gamma[k] * w;
            B += beta[k] * w;
        }
        g_G[c] = G;
        g_B[c] = B;
    }
}

// ---------------- CSR build ----------------
__global__ void hist_k(const int* __restrict__ dst, int e) {
    int i = blockIdx.x * blockDim.x + threadIdx.x;
    if (i < e) atomicAdd(&g_cur[dst[i]], 1);
}

// Phase 1: per-1024-chunk sums. grid = nb, block = 256 (4 elems/thread, int4).
#define SCB 1024
__global__ void bsum_k(int n) {
    __shared__ int wsum[8];
    int b = blockIdx.x, tid = threadIdx.x, lane = tid & 31, wid = tid >> 5;
    int base = b * SCB + tid * 4;
    int4 v = make_int4(0, 0, 0, 0);
    if (base + 3 < n)      v = *(const int4*)&g_cur[base];
    else {
        if (base     < n) v.x = g_cur[base];
        if (base + 1 < n) v.y = g_cur[base + 1];
        if (base + 2 < n) v.z = g_cur[base + 2];
    }
    int s = v.x + v.y + v.z + v.w;
    #pragma unroll
    for (int o = 16; o > 0; o >>= 1) s += __shfl_xor_sync(0xFFFFFFFFu, s, o);
    if (lane == 0) wsum[wid] = s;
    __syncthreads();
    if (wid == 0 && lane < 8) {
        int t = wsum[lane];
        #pragma unroll
        for (int o = 4; o > 0; o >>= 1) t += __shfl_xor_sync(0xFFu, t, o);
        if (lane == 0) g_bsum[b] = t;
    }
}

// Phase 2: exclusive scan of <=64 block sums, 1 block of 64 threads.
__global__ void bscan_k(int nb) {
    __shared__ int w0tot;
    int tid = threadIdx.x, lane = tid & 31, wid = tid >> 5;
    int v = (tid < nb) ? g_bsum[tid] : 0;
    int inc = v;
    #pragma unroll
    for (int o = 1; o < 32; o <<= 1) {
        int t = __shfl_up_sync(0xFFFFFFFFu, inc, o);
        if (lane >= o) inc += t;
    }
    if (wid == 0 && lane == 31) w0tot = inc;
    __syncthreads();
    int ex = inc - v + (wid == 1 ? w0tot : 0);
    if (tid < nb) g_bsum[tid] = ex;
}

// Phase 3: block-local scan + global fixup.
__global__ void scanfin_k(int n) {
    __shared__ int wsum[8];
    int b = blockIdx.x, tid = threadIdx.x, lane = tid & 31, wid = tid >> 5;
    int base = b * SCB + tid * 4;
    int4 v = make_int4(0, 0, 0, 0);
    if (base + 3 < n)      v = *(const int4*)&g_cur[base];
    else {
        if (base     < n) v.x = g_cur[base];
        if (base + 1 < n) v.y = g_cur[base + 1];
        if (base + 2 < n) v.z = g_cur[base + 2];
    }
    int tsum = v.x + v.y + v.z + v.w;
    int inc = tsum;
    #pragma unroll
    for (int o = 1; o < 32; o <<= 1) {
        int t = __shfl_up_sync(0xFFFFFFFFu, inc, o);
        if (lane >= o) inc += t;
    }
    if (lane == 31) wsum[wid] = inc;
    __syncthreads();
    if (wid == 0 && lane < 8) {
        int wv = wsum[lane];
        int wi = wv;
        #pragma unroll
        for (int o = 1; o < 8; o <<= 1) {
            int t = __shfl_up_sync(0xFFu, wi, o);
            if (lane >= o) wi += t;
        }
        wsum[lane] = wi - wv;  // exclusive warp offset
    }
    __syncthreads();
    int e0 = inc - tsum + wsum[wid] + g_bsum[b];
    int e1 = e0 + v.x, e2 = e1 + v.y, e3 = e2 + v.z, e4 = e3 + v.w;
    if (base     < n) { g_cur[base]     = e0; g_off[base + 1] = e1; }
    if (base + 1 < n) { g_cur[base + 1] = e1; g_off[base + 2] = e2; }
    if (base + 2 < n) { g_cur[base + 2] = e2; g_off[base + 3] = e3; }
    if (base + 3 < n) { g_cur[base + 3] = e3; g_off[base + 4] = e4; }
    if (b == 0 && tid == 0) g_off[0] = 0;
}

__global__ void scat_k(const int* __restrict__ src, const int* __restrict__ dst, int e) {
    int i = blockIdx.x * blockDim.x + threadIdx.x;
    if (i < e) {
        int p = atomicAdd(&g_cur[dst[i]], 1);
        g_csr[p] = src[i];
    }
}

// ---------------- fused node kernel: LN + dual GEMM + attention dots ----------------
#define TM 64
#define XT_PITCH 68   // multiple of 4 => every k*XT_PITCH float4-aligned
#define NODE_SMEM_FLOATS (32768 + 128 * XT_PITCH + 64 + 64 + 256 + 128 + 128 + 128)
#define NODE_SMEM_BYTES (NODE_SMEM_FLOATS * 4)

__global__ void __launch_bounds__(256, 1) node_k(
    const float* __restrict__ x, const float* __restrict__ gamma,
    const float* __restrict__ Wgat, const float* __restrict__ Wproj,
    const float* __restrict__ att_src, const float* __restrict__ att_dst,
    const float* __restrict__ bproj, int n)
{
    extern __shared__ float sm[];
    float* Bs    = sm;                       // [128][256]
    float* xT    = Bs + 32768;               // [128][XT_PITCH]
    float* smu   = xT + 128 * XT_PITCH;      // [64]
    float* srstd = smu + TM;                 // [64]
    float* satt  = srstd + TM;               // [256]
    float* sG    = satt + 256;               // [128]
    float* sB    = sG + 128;                 // [128]
    float* sbp   = sB + 128;                 // [128]

    int tid = threadIdx.x;
    int i0 = blockIdx.x * TM;

    for (int t = tid; t < 32768; t += 256) {
        int k = t >> 8, c = t & 255;
        float v;
        if (c < 128) v = gamma[k] * Wgat[k * 128 + c];
        else         v = Wproj[k * 128 + (c - 128)];
        Bs[t] = v;
    }
    if (tid < 128) {
        satt[tid]       = att_src[tid];
        satt[128 + tid] = att_dst[tid];
        sG[tid] = g_G[tid];
        sB[tid] = g_B[tid];
        sbp[tid] = bproj[tid];
    }

    int wid = tid >> 5, lane = tid & 31;
    for (int rr = 0; rr < 8; rr++) {
        int r = wid * 8 + rr;
        int node = i0 + r;
        float4 v = make_float4(0.f, 0.f, 0.f, 0.f);
        if (node < n) v = *(const float4*)&x[(long)node * 128 + lane * 4];
        float s = v.x + v.y + v.z + v.w;
        float q = v.x * v.x + v.y * v.y + v.z * v.z + v.w * v.w;
        #pragma unroll
        for (int o = 16; o > 0; o >>= 1) {
            s += __shfl_xor_sync(0xFFFFFFFFu, s, o);
            q += __shfl_xor_sync(0xFFFFFFFFu, q, o);
        }
        float mu = s * (1.f / 128.f);
        float var = q * (1.f / 128.f) - mu * mu;
        float rstd = rsqrtf(var + 1e-5f);
        if (lane == 0) { smu[r] = mu; srstd[r] = rstd; }
        int kbase = lane * 4;
        xT[(kbase + 0) * XT_PITCH + r] = v.x;
        xT[(kbase + 1) * XT_PITCH + r] = v.y;
        xT[(kbase + 2) * XT_PITCH + r] = v.z;
        xT[(kbase + 3) * XT_PITCH + r] = v.w;
    }
    __syncthreads();

    int ty = tid >> 5;
    int tx = tid & 31;

    unsigned long long acc[32];
    #pragma unroll
    for (int t = 0; t < 32; t++) acc[t] = 0ull;

    const float* xbase = &xT[ty * 8];
    const float* bbase = &Bs[tx * 4];

    #pragma unroll 4
    for (int k = 0; k < 128; k++) {
        float4 a0 = *(const float4*)&xbase[k * XT_PITCH];
        float4 a1 = *(const float4*)&xbase[k * XT_PITCH + 4];
        ulonglong2 B0 = *(const ulonglong2*)&bbase[k * 256];
        ulonglong2 B1 = *(const ulonglong2*)&bbase[k * 256 + 128];
        float af[8] = {a0.x, a0.y, a0.z, a0.w, a1.x, a1.y, a1.z, a1.w};
        #pragma unroll
        for (int i = 0; i < 8; i++) {
            unsigned long long pa = pk2(af[i]);
            fma2(acc[i * 4 + 0], pa, B0.x);
            fma2(acc[i * 4 + 1], pa, B0.y);
            fma2(acc[i * 4 + 2], pa, B1.x);
            fma2(acc[i * 4 + 3], pa, B1.y);
        }
    }

    int h = tx >> 3;
    int ccb = (tx & 7) * 4;
    #pragma unroll
    for (int i = 0; i < 8; i++) {
        int r = ty * 8 + i;
        int node = i0 + r;
        if (node >= n) continue;
        float mu = smu[r], rs = srstd[r];
        float2 v0 = up2(acc[i * 4 + 0]);
        float2 v1 = up2(acc[i * 4 + 1]);
        float2 w0 = up2(acc[i * 4 + 2]);
        float2 w1 = up2(acc[i * 4 + 3]);
        float xwv[4] = {v0.x, v0.y, v1.x, v1.y};
        float idv[4] = {w0.x, w0.y, w1.x, w1.y};
        float ps = 0.f, pd = 0.f;
        float outxw[4];
        #pragma unroll
        for (int j = 0; j < 4; j++) {
            int c = tx * 4 + j;
            float val = rs * (xwv[j] - mu * sG[c]) + sB[c];
            outxw[j] = val;
            ps += val * satt[c];
            pd += val * satt[128 + c];
        }
        long base = (long)node * 128;
        #pragma unroll
        for (int j = 0; j < 4; j++)
            g_xw[base + (ccb + j) * 4 + h] = outxw[j];
        float4 iv = make_float4(idv[0] + sbp[tx * 4 + 0], idv[1] + sbp[tx * 4 + 1],
                                idv[2] + sbp[tx * 4 + 2], idv[3] + sbp[tx * 4 + 3]);
        *(float4*)&g_id[base + tx * 4] = iv;
        #pragma unroll
        for (int o = 1; o < 8; o <<= 1) {
            ps += __shfl_xor_sync(0xFFFFFFFFu, ps, o);
            pd += __shfl_xor_sync(0xFFFFFFFFu, pd, o);
        }
        if ((tx & 7) == 0) {
            g_as[node * 4 + h] = ps;
            g_ad[node * 4 + h] = pd;
        }
    }
}

// ---------------- gather: single-pass softmax (no max shift; scores bounded) ----------------
__device__ __forceinline__ float lrelu(float z) { return z > 0.f ? z : 0.2f * z; }

__global__ void __launch_bounds__(256) gather_k(const float* __restrict__ bias,
                                                float* __restrict__ out, int n)
{
    int gw = (blockIdx.x * 256 + threadIdx.x) >> 5;
    int lane = threadIdx.x & 31;
    if (gw >= n) return;
    int i = gw;
    float4 ad  = *(const float4*)&g_ad[i * 4];
    float4 asi = *(const float4*)&g_as[i * 4];
    int beg = g_off[i], end = g_off[i + 1];

    long myb = (long)i * 128;
    float4 xv = *(const float4*)&g_xw[myb + lane * 4];

    // self-loop term (m = 0; scores are O(1), exp cannot overflow)
    float p0 = __expf(lrelu(asi.x + ad.x));
    float p1 = __expf(lrelu(asi.y + ad.y));
    float p2 = __expf(lrelu(asi.z + ad.z));
    float p3 = __expf(lrelu(asi.w + ad.w));
    float d0 = p0, d1 = p1, d2 = p2, d3 = p3;
    float a0 = p0 * xv.x, a1 = p1 * xv.y, a2 = p2 * xv.z, a3 = p3 * xv.w;

    #pragma unroll 4
    for (int j = beg; j < end; j++) {
        int s = __ldg(&g_csr[j]);
        float4 a4 = *(const float4*)&g_as[s * 4];
        float4 x4 = *(const float4*)&g_xw[(long)s * 128 + lane * 4];
        float q0 = __expf(lrelu(a4.x + ad.x));
        float q1 = __expf(lrelu(a4.y + ad.y));
        float q2 = __expf(lrelu(a4.z + ad.z));
        float q3 = __expf(lrelu(a4.w + ad.w));
        d0 += q0; a0 = fmaf(q0, x4.x, a0);
        d1 += q1; a1 = fmaf(q1, x4.y, a1);
        d2 += q2; a2 = fmaf(q2, x4.z, a2);
        d3 += q3; a3 = fmaf(q3, x4.w, a3);
    }

    float r0 = a0 / (d0 + 1e-16f);
    float r1 = a1 / (d1 + 1e-16f);
    float r2 = a2 / (d2 + 1e-16f);
    float r3 = a3 / (d3 + 1e-16f);

    long ob = myb + lane;
    out[ob +  0] = fmaxf(g_id[ob +  0] + r0 + __ldg(&bias[lane +  0]), 0.f);
    out[ob + 32] = fmaxf(g_id[ob + 32] + r1 + __ldg(&bias[lane + 32]), 0.f);
    out[ob + 64] = fmaxf(g_id[ob + 64] + r2 + __ldg(&bias[lane + 64]), 0.f);
    out[ob + 96] = fmaxf(g_id[ob + 96] + r3 + __ldg(&bias[lane + 96]), 0.f);
}

// ---------------- launch ----------------
extern "C" void kernel_launch(void* const* d_in, const int* in_sizes, int n_in,
                              void* d_out, int out_size)
{
    const float* x        = (const float*)d_in[0];
    const int*   ei       = (const int*)d_in[1];
    const float* gamma    = (const float*)d_in[2];
    const float* beta     = (const float*)d_in[3];
    const float* Wgat     = (const float*)d_in[4];
    const float* att_src  = (const float*)d_in[5];
    const float* att_dst  = (const float*)d_in[6];
    const float* bias_gat = (const float*)d_in[7];
    const float* Wproj    = (const float*)d_in[8];
    const float* bproj    = (const float*)d_in[9];

    int n = in_sizes[0] / 128;
    int e = in_sizes[1] / 2;
    const int* src = ei;
    const int* dst = ei + e;
    int nb = (n + SCB - 1) / SCB;

    void* curp = nullptr;
    cudaGetSymbolAddress(&curp, g_cur);

    cudaFuncSetAttribute(node_k, cudaFuncAttributeMaxDynamicSharedMemorySize, NODE_SMEM_BYTES);

    // Fork a side stream for the CSR pipeline; it is independent of the GEMM
    // path (prep_k -> node_k). Fork/join via events keeps this graph-capturable.
    cudaStream_t s2;
    cudaStreamCreate(&s2);
    cudaEvent_t evFork, evJoin;
    cudaEventCreateWithFlags(&evFork, cudaEventDisableTiming);
    cudaEventCreateWithFlags(&evJoin, cudaEventDisableTiming);

    cudaEventRecord(evFork, 0);
    cudaStreamWaitEvent(s2, evFork, 0);

    // side stream: CSR build
    cudaMemsetAsync(curp, 0, n * sizeof(int), s2);
    hist_k<<<(e + 255) / 256, 256, 0, s2>>>(dst, e);
    bsum_k<<<nb, 256, 0, s2>>>(n);
    bscan_k<<<1, 64, 0, s2>>>(nb);
    scanfin_k<<<nb, 256, 0, s2>>>(n);
    scat_k<<<(e + 255) / 256, 256, 0, s2>>>(src, dst, e);
    cudaEventRecord(evJoin, s2);

    // main stream: GEMM path
    prep_k<<<1, 128>>>(gamma, beta, Wgat);
    node_k<<<(n + TM - 1) / TM, 256, NODE_SMEM_BYTES>>>(x, gamma, Wgat, Wproj,
                                                        att_src, att_dst, bproj, n);

    // join, then gather
    cudaStreamWaitEvent(0, evJoin, 0);
    gather_k<<<(n + 7) / 8, 256>>>(bias_gat, (float*)d_out, n);

    cudaEventDestroy(evFork);
    cudaEventDestroy(evJoin);
    cudaStreamDestroy(s2);
}

// round 5
// speedup vs baseline: 1.3998x; 1.0518x over previous
#include <cuda_runtime.h>
#include <cuda_bf16.h>

// Problem constants (fixed-shape problem)
#define MAXN 50176
#define MAXE 800256

// ---------------- scratch (no allocation allowed; 16B-aligned for vector access) ----------------
__device__ __align__(16) float g_xw[MAXN * 128];   // xw per node, layout [node][cc*4+h]
__device__ __align__(16) float g_id[MAXN * 128];   // identity = x@W_proj + b_proj, layout [node][c]
__device__ __align__(16) float g_as[MAXN * 4];
__device__ __align__(16) float g_ad[MAXN * 4];
__device__ __align__(16) int   g_cur[MAXN];
__device__ int   g_off[MAXN + 1];
__device__ int   g_csr[MAXE];
__device__ int   g_bsum[64];
__device__ float g_G[128];           // colsum of gamma*W_gat
__device__ float g_B[128];           // beta @ W_gat

// ---------------- f32x2 helpers ----------------
__device__ __forceinline__ unsigned long long pk2(float a) {
    unsigned long long r;
    asm("mov.b64 %0, {%1, %1};" : "=l"(r) : "f"(a));
    return r;
}
__device__ __forceinline__ void fma2(unsigned long long &d, unsigned long long a, unsigned long long b) {
    asm("fma.rn.f32x2 %0, %1, %2, %0;" : "+l"(d) : "l"(a), "l"(b));
}
__device__ __forceinline__ float2 up2(unsigned long long v) {
    float2 f;
    asm("mov.b64 {%0, %1}, %2;" : "=f"(f.x), "=f"(f.y) : "l"(v));
    return f;
}

// ---------------- prep: G_c = sum_k gamma_k*Wgat[k][c], B_c = sum_k beta_k*Wgat[k][c] ----------------
__global__ void prep_k(const float* __restrict__ gamma, const float* __restrict__ beta,
                       const float* __restrict__ Wgat) {
    int c = threadIdx.x;
    if (c < 128) {
        float G = 0.f, B = 0.f;
        for (int k = 0; k < 128; k++) {
            float w = Wgat[k * 128 + c];
            G += gamma[k] * w;
            B += beta[k] * w;
        }
        g_G[c] = G;
        g_B[c] = B;
    }
}

// ---------------- CSR build ----------------
__global__ void hist_k(const int* __restrict__ dst, int e) {
    int i = blockIdx.x * blockDim.x + threadIdx.x;
    if (i < e) atomicAdd(&g_cur[dst[i]], 1);
}

// Phase 1: per-1024-chunk sums. grid = nb, block = 256 (4 elems/thread, int4).
#define SCB 1024
__global__ void bsum_k(int n) {
    __shared__ int wsum[8];
    int b = blockIdx.x, tid = threadIdx.x, lane = tid & 31, wid = tid >> 5;
    int base = b * SCB + tid * 4;
    int4 v = make_int4(0, 0, 0, 0);
    if (base + 3 < n)      v = *(const int4*)&g_cur[base];
    else {
        if (base     < n) v.x = g_cur[base];
        if (base + 1 < n) v.y = g_cur[base + 1];
        if (base + 2 < n) v.z = g_cur[base + 2];
    }
    int s = v.x + v.y + v.z + v.w;
    #pragma unroll
    for (int o = 16; o > 0; o >>= 1) s += __shfl_xor_sync(0xFFFFFFFFu, s, o);
    if (lane == 0) wsum[wid] = s;
    __syncthreads();
    if (wid == 0 && lane < 8) {
        int t = wsum[lane];
        #pragma unroll
        for (int o = 4; o > 0; o >>= 1) t += __shfl_xor_sync(0xFFu, t, o);
        if (lane == 0) g_bsum[b] = t;
    }
}

// Phase 2: exclusive scan of <=64 block sums, 1 block of 64 threads.
__global__ void bscan_k(int nb) {
    __shared__ int w0tot;
    int tid = threadIdx.x, lane = tid & 31, wid = tid >> 5;
    int v = (tid < nb) ? g_bsum[tid] : 0;
    int inc = v;
    #pragma unroll
    for (int o = 1; o < 32; o <<= 1) {
        int t = __shfl_up_sync(0xFFFFFFFFu, inc, o);
        if (lane >= o) inc += t;
    }
    if (wid == 0 && lane == 31) w0tot = inc;
    __syncthreads();
    int ex = inc - v + (wid == 1 ? w0tot : 0);
    if (tid < nb) g_bsum[tid] = ex;
}

// Phase 3: block-local scan + global fixup.
__global__ void scanfin_k(int n) {
    __shared__ int wsum[8];
    int b = blockIdx.x, tid = threadIdx.x, lane = tid & 31, wid = tid >> 5;
    int base = b * SCB + tid * 4;
    int4 v = make_int4(0, 0, 0, 0);
    if (base + 3 < n)      v = *(const int4*)&g_cur[base];
    else {
        if (base     < n) v.x = g_cur[base];
        if (base + 1 < n) v.y = g_cur[base + 1];
        if (base + 2 < n) v.z = g_cur[base + 2];
    }
    int tsum = v.x + v.y + v.z + v.w;
    int inc = tsum;
    #pragma unroll
    for (int o = 1; o < 32; o <<= 1) {
        int t = __shfl_up_sync(0xFFFFFFFFu, inc, o);
        if (lane >= o) inc += t;
    }
    if (lane == 31) wsum[wid] = inc;
    __syncthreads();
    if (wid == 0 && lane < 8) {
        int wv = wsum[lane];
        int wi = wv;
        #pragma unroll
        for (int o = 1; o < 8; o <<= 1) {
            int t = __shfl_up_sync(0xFFu, wi, o);
            if (lane >= o) wi += t;
        }
        wsum[lane] = wi - wv;  // exclusive warp offset
    }
    __syncthreads();
    int e0 = inc - tsum + wsum[wid] + g_bsum[b];
    int e1 = e0 + v.x, e2 = e1 + v.y, e3 = e2 + v.z, e4 = e3 + v.w;
    if (base     < n) { g_cur[base]     = e0; g_off[base + 1] = e1; }
    if (base + 1 < n) { g_cur[base + 1] = e1; g_off[base + 2] = e2; }
    if (base + 2 < n) { g_cur[base + 2] = e2; g_off[base + 3] = e3; }
    if (base + 3 < n) { g_cur[base + 3] = e3; g_off[base + 4] = e4; }
    if (b == 0 && tid == 0) g_off[0] = 0;
}

__global__ void scat_k(const int* __restrict__ src, const int* __restrict__ dst, int e) {
    int i = blockIdx.x * blockDim.x + threadIdx.x;
    if (i < e) {
        int p = atomicAdd(&g_cur[dst[i]], 1);
        g_csr[p] = src[i];
    }
}

// ---------------- fused node kernel: LN + dual GEMM + attention dots ----------------
#define TM 64
#define XT_PITCH 68   // multiple of 4 => every k*XT_PITCH float4-aligned
#define NODE_SMEM_FLOATS (32768 + 128 * XT_PITCH + 64 + 64 + 256 + 128 + 128 + 128)
#define NODE_SMEM_BYTES (NODE_SMEM_FLOATS * 4)

__global__ void __launch_bounds__(256, 1) node_k(
    const float* __restrict__ x, const float* __restrict__ gamma,
    const float* __restrict__ Wgat, const float* __restrict__ Wproj,
    const float* __restrict__ att_src, const float* __restrict__ att_dst,
    const float* __restrict__ bproj, int n)
{
    extern __shared__ float sm[];
    float* Bs    = sm;                       // [128][256]
    float* xT    = Bs + 32768;               // [128][XT_PITCH]
    float* smu   = xT + 128 * XT_PITCH;      // [64]
    float* srstd = smu + TM;                 // [64]
    float* satt  = srstd + TM;               // [256]
    float* sG    = satt + 256;               // [128]
    float* sB    = sG + 128;                 // [128]
    float* sbp   = sB + 128;                 // [128]

    int tid = threadIdx.x;
    int i0 = blockIdx.x * TM;

    for (int t = tid; t < 32768; t += 256) {
        int k = t >> 8, c = t & 255;
        float v;
        if (c < 128) v = gamma[k] * Wgat[k * 128 + c];
        else         v = Wproj[k * 128 + (c - 128)];
        Bs[t] = v;
    }
    if (tid < 128) {
        satt[tid]       = att_src[tid];
        satt[128 + tid] = att_dst[tid];
        sG[tid] = g_G[tid];
        sB[tid] = g_B[tid];
        sbp[tid] = bproj[tid];
    }

    int wid = tid >> 5, lane = tid & 31;
    for (int rr = 0; rr < 8; rr++) {
        int r = wid * 8 + rr;
        int node = i0 + r;
        float4 v = make_float4(0.f, 0.f, 0.f, 0.f);
        if (node < n) v = *(const float4*)&x[(long)node * 128 + lane * 4];
        float s = v.x + v.y + v.z + v.w;
        float q = v.x * v.x + v.y * v.y + v.z * v.z + v.w * v.w;
        #pragma unroll
        for (int o = 16; o > 0; o >>= 1) {
            s += __shfl_xor_sync(0xFFFFFFFFu, s, o);
            q += __shfl_xor_sync(0xFFFFFFFFu, q, o);
        }
        float mu = s * (1.f / 128.f);
        float var = q * (1.f / 128.f) - mu * mu;
        float rstd = rsqrtf(var + 1e-5f);
        if (lane == 0) { smu[r] = mu; srstd[r] = rstd; }
        int kbase = lane * 4;
        xT[(kbase + 0) * XT_PITCH + r] = v.x;
        xT[(kbase + 1) * XT_PITCH + r] = v.y;
        xT[(kbase + 2) * XT_PITCH + r] = v.z;
        xT[(kbase + 3) * XT_PITCH + r] = v.w;
    }
    __syncthreads();

    int ty = tid >> 5;
    int tx = tid & 31;

    unsigned long long acc[32];
    #pragma unroll
    for (int t = 0; t < 32; t++) acc[t] = 0ull;

    const float* xbase = &xT[ty * 8];
    const float* bbase = &Bs[tx * 4];

    #pragma unroll 4
    for (int k = 0; k < 128; k++) {
        float4 a0 = *(const float4*)&xbase[k * XT_PITCH];
        float4 a1 = *(const float4*)&xbase[k * XT_PITCH + 4];
        ulonglong2 B0 = *(const ulonglong2*)&bbase[k * 256];
        ulonglong2 B1 = *(const ulonglong2*)&bbase[k * 256 + 128];
        float af[8] = {a0.x, a0.y, a0.z, a0.w, a1.x, a1.y, a1.z, a1.w};
        #pragma unroll
        for (int i = 0; i < 8; i++) {
            unsigned long long pa = pk2(af[i]);
            fma2(acc[i * 4 + 0], pa, B0.x);
            fma2(acc[i * 4 + 1], pa, B0.y);
            fma2(acc[i * 4 + 2], pa, B1.x);
            fma2(acc[i * 4 + 3], pa, B1.y);
        }
    }

    int h = tx >> 3;
    int ccb = (tx & 7) * 4;
    #pragma unroll
    for (int i = 0; i < 8; i++) {
        int r = ty * 8 + i;
        int node = i0 + r;
        if (node >= n) continue;
        float mu = smu[r], rs = srstd[r];
        float2 v0 = up2(acc[i * 4 + 0]);
        float2 v1 = up2(acc[i * 4 + 1]);
        float2 w0 = up2(acc[i * 4 + 2]);
        float2 w1 = up2(acc[i * 4 + 3]);
        float xwv[4] = {v0.x, v0.y, v1.x, v1.y};
        float idv[4] = {w0.x, w0.y, w1.x, w1.y};
        float ps = 0.f, pd = 0.f;
        float outxw[4];
        #pragma unroll
        for (int j = 0; j < 4; j++) {
            int c = tx * 4 + j;
            float val = rs * (xwv[j] - mu * sG[c]) + sB[c];
            outxw[j] = val;
            ps += val * satt[c];
            pd += val * satt[128 + c];
        }
        long base = (long)node * 128;
        #pragma unroll
        for (int j = 0; j < 4; j++)
            g_xw[base + (ccb + j) * 4 + h] = outxw[j];
        float4 iv = make_float4(idv[0] + sbp[tx * 4 + 0], idv[1] + sbp[tx * 4 + 1],
                                idv[2] + sbp[tx * 4 + 2], idv[3] + sbp[tx * 4 + 3]);
        *(float4*)&g_id[base + tx * 4] = iv;
        #pragma unroll
        for (int o = 1; o < 8; o <<= 1) {
            ps += __shfl_xor_sync(0xFFFFFFFFu, ps, o);
            pd += __shfl_xor_sync(0xFFFFFFFFu, pd, o);
        }
        if ((tx & 7) == 0) {
            g_as[node * 4 + h] = ps;
            g_ad[node * 4 + h] = pd;
        }
    }
}

// ---------------- gather: chunked two-phase softmax aggregate ----------------
// Phase A: 32 lanes each handle one edge (coalesced csr load, per-edge exps).
// Phase B: iterate staged edges; broadcast q from smem; lanes fma their 4 channels.
__device__ __forceinline__ float lrelu(float z) { return z > 0.f ? z : 0.2f * z; }

__global__ void __launch_bounds__(256) gather_k(const float* __restrict__ bias,
                                                float* __restrict__ out, int n)
{
    __shared__ float4 sq[8][32];
    __shared__ int    ss[8][32];
    int w = threadIdx.x >> 5;
    int lane = threadIdx.x & 31;
    int i = blockIdx.x * 8 + w;
    if (i >= n) return;

    float4 ad  = *(const float4*)&g_ad[i * 4];
    float4 asi = *(const float4*)&g_as[i * 4];
    int beg = g_off[i], end = g_off[i + 1];

    long myb = (long)i * 128;
    float4 xv = *(const float4*)&g_xw[myb + lane * 4];

    // self-loop term (m = 0; scores are O(1), exp cannot overflow)
    float p0 = __expf(lrelu(asi.x + ad.x));
    float p1 = __expf(lrelu(asi.y + ad.y));
    float p2 = __expf(lrelu(asi.z + ad.z));
    float p3 = __expf(lrelu(asi.w + ad.w));
    float d0 = p0, d1 = p1, d2 = p2, d3 = p3;
    float a0 = p0 * xv.x, a1 = p1 * xv.y, a2 = p2 * xv.z, a3 = p3 * xv.w;

    for (int cs = beg; cs < end; cs += 32) {
        int cnt = min(32, end - cs);
        int j = cs + lane;
        if (lane < cnt) {
            int s = __ldg(&g_csr[j]);
            float4 a4 = *(const float4*)&g_as[s * 4];
            float4 q;
            q.x = __expf(lrelu(a4.x + ad.x));
            q.y = __expf(lrelu(a4.y + ad.y));
            q.z = __expf(lrelu(a4.z + ad.z));
            q.w = __expf(lrelu(a4.w + ad.w));
            ss[w][lane] = s;
            sq[w][lane] = q;
        }
        __syncwarp();
        #pragma unroll 4
        for (int t = 0; t < cnt; t++) {
            int st = ss[w][t];
            float4 qt = sq[w][t];
            float4 x4 = *(const float4*)&g_xw[(long)st * 128 + lane * 4];
            d0 += qt.x; a0 = fmaf(qt.x, x4.x, a0);
            d1 += qt.y; a1 = fmaf(qt.y, x4.y, a1);
            d2 += qt.z; a2 = fmaf(qt.z, x4.z, a2);
            d3 += qt.w; a3 = fmaf(qt.w, x4.w, a3);
        }
        __syncwarp();
    }

    float r0 = a0 / (d0 + 1e-16f);
    float r1 = a1 / (d1 + 1e-16f);
    float r2 = a2 / (d2 + 1e-16f);
    float r3 = a3 / (d3 + 1e-16f);

    long ob = myb + lane;
    out[ob +  0] = fmaxf(g_id[ob +  0] + r0 + __ldg(&bias[lane +  0]), 0.f);
    out[ob + 32] = fmaxf(g_id[ob + 32] + r1 + __ldg(&bias[lane + 32]), 0.f);
    out[ob + 64] = fmaxf(g_id[ob + 64] + r2 + __ldg(&bias[lane + 64]), 0.f);
    out[ob + 96] = fmaxf(g_id[ob + 96] + r3 + __ldg(&bias[lane + 96]), 0.f);
}

// ---------------- launch ----------------
extern "C" void kernel_launch(void* const* d_in, const int* in_sizes, int n_in,
                              void* d_out, int out_size)
{
    const float* x        = (const float*)d_in[0];
    const int*   ei       = (const int*)d_in[1];
    const float* gamma    = (const float*)d_in[2];
    const float* beta     = (const float*)d_in[3];
    const float* Wgat     = (const float*)d_in[4];
    const float* att_src  = (const float*)d_in[5];
    const float* att_dst  = (const float*)d_in[6];
    const float* bias_gat = (const float*)d_in[7];
    const float* Wproj    = (const float*)d_in[8];
    const float* bproj    = (const float*)d_in[9];

    int n = in_sizes[0] / 128;
    int e = in_sizes[1] / 2;
    const int* src = ei;
    const int* dst = ei + e;
    int nb = (n + SCB - 1) / SCB;

    void* curp = nullptr;
    cudaGetSymbolAddress(&curp, g_cur);

    cudaFuncSetAttribute(node_k, cudaFuncAttributeMaxDynamicSharedMemorySize, NODE_SMEM_BYTES);

    // Fork a side stream for the CSR pipeline; it is independent of the GEMM
    // path (prep_k -> node_k). Fork/join via events keeps this graph-capturable.
    cudaStream_t s2;
    cudaStreamCreate(&s2);
    cudaEvent_t evFork, evJoin;
    cudaEventCreateWithFlags(&evFork, cudaEventDisableTiming);
    cudaEventCreateWithFlags(&evJoin, cudaEventDisableTiming);

    cudaEventRecord(evFork, 0);
    cudaStreamWaitEvent(s2, evFork, 0);

    // side stream: CSR build
    cudaMemsetAsync(curp, 0, n * sizeof(int), s2);
    hist_k<<<(e + 255) / 256, 256, 0, s2>>>(dst, e);
    bsum_k<<<nb, 256, 0, s2>>>(n);
    bscan_k<<<1, 64, 0, s2>>>(nb);
    scanfin_k<<<nb, 256, 0, s2>>>(n);
    scat_k<<<(e + 255) / 256, 256, 0, s2>>>(src, dst, e);
    cudaEventRecord(evJoin, s2);

    // main stream: GEMM path
    prep_k<<<1, 128>>>(gamma, beta, Wgat);
    node_k<<<(n + TM - 1) / TM, 256, NODE_SMEM_BYTES>>>(x, gamma, Wgat, Wproj,
                                                        att_src, att_dst, bproj, n);

    // join, then gather
    cudaStreamWaitEvent(0, evJoin, 0);
    gather_k<<<(n + 7) / 8, 256>>>(bias_gat, (float*)d_out, n);

    cudaEventDestroy(evFork);
    cudaEventDestroy(evJoin);
    cudaStreamDestroy(s2);
}

// round 6
// speedup vs baseline: 1.4732x; 1.0524x over previous
#include <cuda_runtime.h>
#include <cuda_bf16.h>
#include <cuda_fp16.h>

// Problem constants (fixed-shape problem)
#define MAXN 50176
#define MAXE 800256

// ---------------- scratch (no allocation allowed; 16B-aligned for vector access) ----------------
__device__ __align__(16) __half g_xwh[MAXN * 128]; // xw per node (fp16), layout [node][cc*4+h]
__device__ __align__(16) float g_id[MAXN * 128];   // identity = x@W_proj + b_proj, layout [node][c]
__device__ __align__(16) float g_as[MAXN * 4];
__device__ __align__(16) float g_ad[MAXN * 4];
__device__ __align__(16) int   g_cur[MAXN];
__device__ int   g_off[MAXN + 1];
__device__ int   g_csr[MAXE];
__device__ int   g_bsum[64];
__device__ float g_G[128];           // colsum of gamma*W_gat
__device__ float g_B[128];           // beta @ W_gat

// ---------------- f32x2 helpers ----------------
__device__ __forceinline__ unsigned long long pk2(float a) {
    unsigned long long r;
    asm("mov.b64 %0, {%1, %1};" : "=l"(r) : "f"(a));
    return r;
}
__device__ __forceinline__ void fma2(unsigned long long &d, unsigned long long a, unsigned long long b) {
    asm("fma.rn.f32x2 %0, %1, %2, %0;" : "+l"(d) : "l"(a), "l"(b));
}
__device__ __forceinline__ float2 up2(unsigned long long v) {
    float2 f;
    asm("mov.b64 {%0, %1}, %2;" : "=f"(f.x), "=f"(f.y) : "l"(v));
    return f;
}

// ---------------- prep ----------------
__global__ void prep_k(const float* __restrict__ gamma, const float* __restrict__ beta,
                       const float* __restrict__ Wgat) {
    int c = threadIdx.x;
    if (c < 128) {
        float G = 0.f, B = 0.f;
        for (int k = 0; k < 128; k++) {
            float w = Wgat[k * 128 + c];
            G += gamma[k] * w;
            B += beta[k] * w;
        }
        g_G[c] = G;
        g_B[c] = B;
    }
}

// ---------------- CSR build ----------------
__global__ void hist_k(const int* __restrict__ dst, int e) {
    int i = blockIdx.x * blockDim.x + threadIdx.x;
    if (i < e) atomicAdd(&g_cur[dst[i]], 1);
}

#define SCB 1024
__global__ void bsum_k(int n) {
    __shared__ int wsum[8];
    int b = blockIdx.x, tid = threadIdx.x, lane = tid & 31, wid = tid >> 5;
    int base = b * SCB + tid * 4;
    int4 v = make_int4(0, 0, 0, 0);
    if (base + 3 < n)      v = *(const int4*)&g_cur[base];
    else {
        if (base     < n) v.x = g_cur[base];
        if (base + 1 < n) v.y = g_cur[base + 1];
        if (base + 2 < n) v.z = g_cur[base + 2];
    }
    int s = v.x + v.y + v.z + v.w;
    #pragma unroll
    for (int o = 16; o > 0; o >>= 1) s += __shfl_xor_sync(0xFFFFFFFFu, s, o);
    if (lane == 0) wsum[wid] = s;
    __syncthreads();
    if (wid == 0 && lane < 8) {
        int t = wsum[lane];
        #pragma unroll
        for (int o = 4; o > 0; o >>= 1) t += __shfl_xor_sync(0xFFu, t, o);
        if (lane == 0) g_bsum[b] = t;
    }
}

__global__ void bscan_k(int nb) {
    __shared__ int w0tot;
    int tid = threadIdx.x, lane = tid & 31, wid = tid >> 5;
    int v = (tid < nb) ? g_bsum[tid] : 0;
    int inc = v;
    #pragma unroll
    for (int o = 1; o < 32; o <<= 1) {
        int t = __shfl_up_sync(0xFFFFFFFFu, inc, o);
        if (lane >= o) inc += t;
    }
    if (wid == 0 && lane == 31) w0tot = inc;
    __syncthreads();
    int ex = inc - v + (wid == 1 ? w0tot : 0);
    if (tid < nb) g_bsum[tid] = ex;
}

__global__ void scanfin_k(int n) {
    __shared__ int wsum[8];
    int b = blockIdx.x, tid = threadIdx.x, lane = tid & 31, wid = tid >> 5;
    int base = b * SCB + tid * 4;
    int4 v = make_int4(0, 0, 0, 0);
    if (base + 3 < n)      v = *(const int4*)&g_cur[base];
    else {
        if (base     < n) v.x = g_cur[base];
        if (base + 1 < n) v.y = g_cur[base + 1];
        if (base + 2 < n) v.z = g_cur[base + 2];
    }
    int tsum = v.x + v.y + v.z + v.w;
    int inc = tsum;
    #pragma unroll
    for (int o = 1; o < 32; o <<= 1) {
        int t = __shfl_up_sync(0xFFFFFFFFu, inc, o);
        if (lane >= o) inc += t;
    }
    if (lane == 31) wsum[wid] = inc;
    __syncthreads();
    if (wid == 0 && lane < 8) {
        int wv = wsum[lane];
        int wi = wv;
        #pragma unroll
        for (int o = 1; o < 8; o <<= 1) {
            int t = __shfl_up_sync(0xFFu, wi, o);
            if (lane >= o) wi += t;
        }
        wsum[lane] = wi - wv;
    }
    __syncthreads();
    int e0 = inc - tsum + wsum[wid] + g_bsum[b];
    int e1 = e0 + v.x, e2 = e1 + v.y, e3 = e2 + v.z, e4 = e3 + v.w;
    if (base     < n) { g_cur[base]     = e0; g_off[base + 1] = e1; }
    if (base + 1 < n) { g_cur[base + 1] = e1; g_off[base + 2] = e2; }
    if (base + 2 < n) { g_cur[base + 2] = e2; g_off[base + 3] = e3; }
    if (base + 3 < n) { g_cur[base + 3] = e3; g_off[base + 4] = e4; }
    if (b == 0 && tid == 0) g_off[0] = 0;
}

__global__ void scat_k(const int* __restrict__ src, const int* __restrict__ dst, int e) {
    int i = blockIdx.x * blockDim.x + threadIdx.x;
    if (i < e) {
        int p = atomicAdd(&g_cur[dst[i]], 1);
        g_csr[p] = src[i];
    }
}

// ---------------- fused node kernel: LN + dual GEMM + attention dots ----------------
#define TM 64
#define XT_PITCH 68
#define NODE_SMEM_FLOATS (32768 + 128 * XT_PITCH + 64 + 64 + 256 + 128 + 128 + 128)
#define NODE_SMEM_BYTES (NODE_SMEM_FLOATS * 4)

__global__ void __launch_bounds__(256, 1) node_k(
    const float* __restrict__ x, const float* __restrict__ gamma,
    const float* __restrict__ Wgat, const float* __restrict__ Wproj,
    const float* __restrict__ att_src, const float* __restrict__ att_dst,
    const float* __restrict__ bproj, int n)
{
    extern __shared__ float sm[];
    float* Bs    = sm;
    float* xT    = Bs + 32768;
    float* smu   = xT + 128 * XT_PITCH;
    float* srstd = smu + TM;
    float* satt  = srstd + TM;
    float* sG    = satt + 256;
    float* sB    = sG + 128;
    float* sbp   = sB + 128;

    int tid = threadIdx.x;
    int i0 = blockIdx.x * TM;

    for (int t = tid; t < 32768; t += 256) {
        int k = t >> 8, c = t & 255;
        float v;
        if (c < 128) v = gamma[k] * Wgat[k * 128 + c];
        else         v = Wproj[k * 128 + (c - 128)];
        Bs[t] = v;
    }
    if (tid < 128) {
        satt[tid]       = att_src[tid];
        satt[128 + tid] = att_dst[tid];
        sG[tid] = g_G[tid];
        sB[tid] = g_B[tid];
        sbp[tid] = bproj[tid];
    }

    int wid = tid >> 5, lane = tid & 31;
    for (int rr = 0; rr < 8; rr++) {
        int r = wid * 8 + rr;
        int node = i0 + r;
        float4 v = make_float4(0.f, 0.f, 0.f, 0.f);
        if (node < n) v = *(const float4*)&x[(long)node * 128 + lane * 4];
        float s = v.x + v.y + v.z + v.w;
        float q = v.x * v.x + v.y * v.y + v.z * v.z + v.w * v.w;
        #pragma unroll
        for (int o = 16; o > 0; o >>= 1) {
            s += __shfl_xor_sync(0xFFFFFFFFu, s, o);
            q += __shfl_xor_sync(0xFFFFFFFFu, q, o);
        }
        float mu = s * (1.f / 128.f);
        float var = q * (1.f / 128.f) - mu * mu;
        float rstd = rsqrtf(var + 1e-5f);
        if (lane == 0) { smu[r] = mu; srstd[r] = rstd; }
        int kbase = lane * 4;
        xT[(kbase + 0) * XT_PITCH + r] = v.x;
        xT[(kbase + 1) * XT_PITCH + r] = v.y;
        xT[(kbase + 2) * XT_PITCH + r] = v.z;
        xT[(kbase + 3) * XT_PITCH + r] = v.w;
    }
    __syncthreads();

    int ty = tid >> 5;
    int tx = tid & 31;

    unsigned long long acc[32];
    #pragma unroll
    for (int t = 0; t < 32; t++) acc[t] = 0ull;

    const float* xbase = &xT[ty * 8];
    const float* bbase = &Bs[tx * 4];

    #pragma unroll 4
    for (int k = 0; k < 128; k++) {
        float4 a0 = *(const float4*)&xbase[k * XT_PITCH];
        float4 a1 = *(const float4*)&xbase[k * XT_PITCH + 4];
        ulonglong2 B0 = *(const ulonglong2*)&bbase[k * 256];
        ulonglong2 B1 = *(const ulonglong2*)&bbase[k * 256 + 128];
        float af[8] = {a0.x, a0.y, a0.z, a0.w, a1.x, a1.y, a1.z, a1.w};
        #pragma unroll
        for (int i = 0; i < 8; i++) {
            unsigned long long pa = pk2(af[i]);
            fma2(acc[i * 4 + 0], pa, B0.x);
            fma2(acc[i * 4 + 1], pa, B0.y);
            fma2(acc[i * 4 + 2], pa, B1.x);
            fma2(acc[i * 4 + 3], pa, B1.y);
        }
    }

    int h = tx >> 3;
    int ccb = (tx & 7) * 4;
    #pragma unroll
    for (int i = 0; i < 8; i++) {
        int r = ty * 8 + i;
        int node = i0 + r;
        if (node >= n) continue;
        float mu = smu[r], rs = srstd[r];
        float2 v0 = up2(acc[i * 4 + 0]);
        float2 v1 = up2(acc[i * 4 + 1]);
        float2 w0 = up2(acc[i * 4 + 2]);
        float2 w1 = up2(acc[i * 4 + 3]);
        float xwv[4] = {v0.x, v0.y, v1.x, v1.y};
        float idv[4] = {w0.x, w0.y, w1.x, w1.y};
        float ps = 0.f, pd = 0.f;
        float outxw[4];
        #pragma unroll
        for (int j = 0; j < 4; j++) {
            int c = tx * 4 + j;
            float val = rs * (xwv[j] - mu * sG[c]) + sB[c];
            outxw[j] = val;
            ps += val * satt[c];
            pd += val * satt[128 + c];
        }
        long base = (long)node * 128;
        #pragma unroll
        for (int j = 0; j < 4; j++)
            g_xwh[base + (ccb + j) * 4 + h] = __float2half_rn(outxw[j]);
        float4 iv = make_float4(idv[0] + sbp[tx * 4 + 0], idv[1] + sbp[tx * 4 + 1],
                                idv[2] + sbp[tx * 4 + 2], idv[3] + sbp[tx * 4 + 3]);
        *(float4*)&g_id[base + tx * 4] = iv;
        #pragma unroll
        for (int o = 1; o < 8; o <<= 1) {
            ps += __shfl_xor_sync(0xFFFFFFFFu, ps, o);
            pd += __shfl_xor_sync(0xFFFFFFFFu, pd, o);
        }
        if ((tx & 7) == 0) {
            g_as[node * 4 + h] = ps;
            g_ad[node * 4 + h] = pd;
        }
    }
}

// ---------------- gather: chunked two-phase softmax aggregate (fp16 values) ----------------
__device__ __forceinline__ float lrelu(float z) { return z > 0.f ? z : 0.2f * z; }

__device__ __forceinline__ float4 ldxw_h(long idx128, int lane) {
    const __half* p = g_xwh + idx128 + lane * 4;
    uint2 u = *(const uint2*)p;
    __half2 h0 = *reinterpret_cast<__half2*>(&u.x);
    __half2 h1 = *reinterpret_cast<__half2*>(&u.y);
    float2 f0 = __half22float2(h0);
    float2 f1 = __half22float2(h1);
    return make_float4(f0.x, f0.y, f1.x, f1.y);
}

__global__ void __launch_bounds__(256) gather_k(const float* __restrict__ bias,
                                                float* __restrict__ out, int n)
{
    __shared__ float4 sq[8][32];
    __shared__ int    ss[8][32];
    int w = threadIdx.x >> 5;
    int lane = threadIdx.x & 31;
    int i = blockIdx.x * 8 + w;
    if (i >= n) return;

    float4 ad  = *(const float4*)&g_ad[i * 4];
    float4 asi = *(const float4*)&g_as[i * 4];
    int beg = g_off[i], end = g_off[i + 1];

    long myb = (long)i * 128;
    float4 xv = ldxw_h(myb, lane);

    float p0 = __expf(lrelu(asi.x + ad.x));
    float p1 = __expf(lrelu(asi.y + ad.y));
    float p2 = __expf(lrelu(asi.z + ad.z));
    float p3 = __expf(lrelu(asi.w + ad.w));
    float d0 = p0, d1 = p1, d2 = p2, d3 = p3;
    float a0 = p0 * xv.x, a1 = p1 * xv.y, a2 = p2 * xv.z, a3 = p3 * xv.w;

    for (int cs = beg; cs < end; cs += 32) {
        int cnt = min(32, end - cs);
        int j = cs + lane;
        if (lane < cnt) {
            int s = __ldg(&g_csr[j]);
            float4 a4 = *(const float4*)&g_as[s * 4];
            float4 q;
            q.x = __expf(lrelu(a4.x + ad.x));
            q.y = __expf(lrelu(a4.y + ad.y));
            q.z = __expf(lrelu(a4.z + ad.z));
            q.w = __expf(lrelu(a4.w + ad.w));
            ss[w][lane] = s;
            sq[w][lane] = q;
        }
        __syncwarp();
        #pragma unroll 4
        for (int t = 0; t < cnt; t++) {
            int st = ss[w][t];
            float4 qt = sq[w][t];
            float4 x4 = ldxw_h((long)st * 128, lane);
            d0 += qt.x; a0 = fmaf(qt.x, x4.x, a0);
            d1 += qt.y; a1 = fmaf(qt.y, x4.y, a1);
            d2 += qt.z; a2 = fmaf(qt.z, x4.z, a2);
            d3 += qt.w; a3 = fmaf(qt.w, x4.w, a3);
        }
        __syncwarp();
    }

    float r0 = a0 / (d0 + 1e-16f);
    float r1 = a1 / (d1 + 1e-16f);
    float r2 = a2 / (d2 + 1e-16f);
    float r3 = a3 / (d3 + 1e-16f);

    long ob = myb + lane;
    out[ob +  0] = fmaxf(g_id[ob +  0] + r0 + __ldg(&bias[lane +  0]), 0.f);
    out[ob + 32] = fmaxf(g_id[ob + 32] + r1 + __ldg(&bias[lane + 32]), 0.f);
    out[ob + 64] = fmaxf(g_id[ob + 64] + r2 + __ldg(&bias[lane + 64]), 0.f);
    out[ob + 96] = fmaxf(g_id[ob + 96] + r3 + __ldg(&bias[lane + 96]), 0.f);
}

// ---------------- launch ----------------
extern "C" void kernel_launch(void* const* d_in, const int* in_sizes, int n_in,
                              void* d_out, int out_size)
{
    const float* x        = (const float*)d_in[0];
    const int*   ei       = (const int*)d_in[1];
    const float* gamma    = (const float*)d_in[2];
    const float* beta     = (const float*)d_in[3];
    const float* Wgat     = (const float*)d_in[4];
    const float* att_src  = (const float*)d_in[5];
    const float* att_dst  = (const float*)d_in[6];
    const float* bias_gat = (const float*)d_in[7];
    const float* Wproj    = (const float*)d_in[8];
    const float* bproj    = (const float*)d_in[9];

    int n = in_sizes[0] / 128;
    int e = in_sizes[1] / 2;
    const int* src = ei;
    const int* dst = ei + e;
    int nb = (n + SCB - 1) / SCB;

    void* curp = nullptr;
    cudaGetSymbolAddress(&curp, g_cur);

    cudaFuncSetAttribute(node_k, cudaFuncAttributeMaxDynamicSharedMemorySize, NODE_SMEM_BYTES);

    cudaStream_t s2;
    cudaStreamCreate(&s2);
    cudaEvent_t evFork, evJoin;
    cudaEventCreateWithFlags(&evFork, cudaEventDisableTiming);
    cudaEventCreateWithFlags(&evJoin, cudaEventDisableTiming);

    cudaEventRecord(evFork, 0);
    cudaStreamWaitEvent(s2, evFork, 0);

    // side stream: CSR build
    cudaMemsetAsync(curp, 0, n * sizeof(int), s2);
    hist_k<<<(e + 255) / 256, 256, 0, s2>>>(dst, e);
    bsum_k<<<nb, 256, 0, s2>>>(n);
    bscan_k<<<1, 64, 0, s2>>>(nb);
    scanfin_k<<<nb, 256, 0, s2>>>(n);
    scat_k<<<(e + 255) / 256, 256, 0, s2>>>(src, dst, e);
    cudaEventRecord(evJoin, s2);

    // main stream: GEMM path
    prep_k<<<1, 128>>>(gamma, beta, Wgat);
    node_k<<<(n + TM - 1) / TM, 256, NODE_SMEM_BYTES>>>(x, gamma, Wgat, Wproj,
                                                        att_src, att_dst, bproj, n);

    cudaStreamWaitEvent(0, evJoin, 0);
    gather_k<<<(n + 7) / 8, 256>>>(bias_gat, (float*)d_out, n);

    cudaEventDestroy(evFork);
    cudaEventDestroy(evJoin);
    cudaStreamDestroy(s2);
}

// round 7
// speedup vs baseline: 2.0404x; 1.3850x over previous
#include <cuda_runtime.h>
#include <cuda_bf16.h>
#include <cuda_fp16.h>

// Problem constants (fixed-shape problem)
#define MAXN 50176
#define MAXE 800256

// ---------------- scratch ----------------
__device__ __align__(16) __half g_xwh[MAXN * 128]; // xw per node (fp16), layout [node][cc*4+h]
__device__ __align__(16) float g_id[MAXN * 128];   // identity = x@W_proj + b_proj, layout [node][c]
__device__ __align__(16) float g_as[MAXN * 4];
__device__ __align__(16) float g_ad[MAXN * 4];
__device__ __align__(16) int   g_cur[MAXN];
__device__ int   g_off[MAXN + 1];
__device__ int   g_csr[MAXE];
__device__ int   g_bsum[64];
__device__ float g_G[128];                          // colsum of gamma*W_gat
__device__ float g_B[128];                          // beta @ W_gat
__device__ __align__(16) float g_Bhi[128 * 256];    // tf32-hi of [gamma*Wgat | Wproj], [k][c]
__device__ __align__(16) float g_Blo[128 * 256];    // tf32-lo residual

// ---------------- tf32 / mma helpers ----------------
__device__ __forceinline__ unsigned tf32u(float x) {
    unsigned r; asm("cvt.rna.tf32.f32 %0, %1;" : "=r"(r) : "f"(x)); return r;
}
__device__ __forceinline__ void mma1688(float* c, const unsigned* a, const unsigned* b) {
    asm volatile("mma.sync.aligned.m16n8k8.row.col.f32.tf32.tf32.f32 "
        "{%0,%1,%2,%3},{%4,%5,%6,%7},{%8,%9},{%0,%1,%2,%3};"
        : "+f"(c[0]), "+f"(c[1]), "+f"(c[2]), "+f"(c[3])
        : "r"(a[0]), "r"(a[1]), "r"(a[2]), "r"(a[3]), "r"(b[0]), "r"(b[1]));
}
__device__ __forceinline__ void cpa16(unsigned s, const float* g) {
    asm volatile("cp.async.ca.shared.global [%0], [%1], 16;" :: "r"(s), "l"(g));
}

// ---------------- prep: G, B colsums ----------------
__global__ void prep_k(const float* __restrict__ gamma, const float* __restrict__ beta,
                       const float* __restrict__ Wgat) {
    int c = threadIdx.x;
    if (c < 128) {
        float G = 0.f, B = 0.f;
        for (int k = 0; k < 128; k++) {
            float w = Wgat[k * 128 + c];
            G += gamma[k] * w;
            B += beta[k] * w;
        }
        g_G[c] = G;
        g_B[c] = B;
    }
}

// prep2: tf32 hi/lo split of the fused weight matrix [gamma*Wgat | Wproj]
__global__ void prep2_k(const float* __restrict__ gamma, const float* __restrict__ Wgat,
                        const float* __restrict__ Wproj) {
    int k = blockIdx.x;          // 0..127
    int c = threadIdx.x;         // 0..255
    float w;
    if (c < 128) w = gamma[k] * Wgat[k * 128 + c];
    else         w = Wproj[k * 128 + (c - 128)];
    float hi = __uint_as_float(tf32u(w));
    float lo = __uint_as_float(tf32u(w - hi));
    g_Bhi[k * 256 + c] = hi;
    g_Blo[k * 256 + c] = lo;
}

// ---------------- CSR build ----------------
__global__ void hist_k(const int* __restrict__ dst, int e) {
    int i = blockIdx.x * blockDim.x + threadIdx.x;
    if (i < e) atomicAdd(&g_cur[dst[i]], 1);
}

#define SCB 1024
__global__ void bsum_k(int n) {
    __shared__ int wsum[8];
    int b = blockIdx.x, tid = threadIdx.x, lane = tid & 31, wid = tid >> 5;
    int base = b * SCB + tid * 4;
    int4 v = make_int4(0, 0, 0, 0);
    if (base + 3 < n)      v = *(const int4*)&g_cur[base];
    else {
        if (base     < n) v.x = g_cur[base];
        if (base + 1 < n) v.y = g_cur[base + 1];
        if (base + 2 < n) v.z = g_cur[base + 2];
    }
    int s = v.x + v.y + v.z + v.w;
    #pragma unroll
    for (int o = 16; o > 0; o >>= 1) s += __shfl_xor_sync(0xFFFFFFFFu, s, o);
    if (lane == 0) wsum[wid] = s;
    __syncthreads();
    if (wid == 0 && lane < 8) {
        int t = wsum[lane];
        #pragma unroll
        for (int o = 4; o > 0; o >>= 1) t += __shfl_xor_sync(0xFFu, t, o);
        if (lane == 0) g_bsum[b] = t;
    }
}

__global__ void bscan_k(int nb) {
    __shared__ int w0tot;
    int tid = threadIdx.x, lane = tid & 31, wid = tid >> 5;
    int v = (tid < nb) ? g_bsum[tid] : 0;
    int inc = v;
    #pragma unroll
    for (int o = 1; o < 32; o <<= 1) {
        int t = __shfl_up_sync(0xFFFFFFFFu, inc, o);
        if (lane >= o) inc += t;
    }
    if (wid == 0 && lane == 31) w0tot = inc;
    __syncthreads();
    int ex = inc - v + (wid == 1 ? w0tot : 0);
    if (tid < nb) g_bsum[tid] = ex;
}

__global__ void scanfin_k(int n) {
    __shared__ int wsum[8];
    int b = blockIdx.x, tid = threadIdx.x, lane = tid & 31, wid = tid >> 5;
    int base = b * SCB + tid * 4;
    int4 v = make_int4(0, 0, 0, 0);
    if (base + 3 < n)      v = *(const int4*)&g_cur[base];
    else {
        if (base     < n) v.x = g_cur[base];
        if (base + 1 < n) v.y = g_cur[base + 1];
        if (base + 2 < n) v.z = g_cur[base + 2];
    }
    int tsum = v.x + v.y + v.z + v.w;
    int inc = tsum;
    #pragma unroll
    for (int o = 1; o < 32; o <<= 1) {
        int t = __shfl_up_sync(0xFFFFFFFFu, inc, o);
        if (lane >= o) inc += t;
    }
    if (lane == 31) wsum[wid] = inc;
    __syncthreads();
    if (wid == 0 && lane < 8) {
        int wv = wsum[lane];
        int wi = wv;
        #pragma unroll
        for (int o = 1; o < 8; o <<= 1) {
            int t = __shfl_up_sync(0xFFu, wi, o);
            if (lane >= o) wi += t;
        }
        wsum[lane] = wi - wv;
    }
    __syncthreads();
    int e0 = inc - tsum + wsum[wid] + g_bsum[b];
    int e1 = e0 + v.x, e2 = e1 + v.y, e3 = e2 + v.z, e4 = e3 + v.w;
    if (base     < n) { g_cur[base]     = e0; g_off[base + 1] = e1; }
    if (base + 1 < n) { g_cur[base + 1] = e1; g_off[base + 2] = e2; }
    if (base + 2 < n) { g_cur[base + 2] = e2; g_off[base + 3] = e3; }
    if (base + 3 < n) { g_cur[base + 3] = e3; g_off[base + 4] = e4; }
    if (b == 0 && tid == 0) g_off[0] = 0;
}

__global__ void scat_k(const int* __restrict__ src, const int* __restrict__ dst, int e) {
    int i = blockIdx.x * blockDim.x + threadIdx.x;
    if (i < e) {
        int p = atomicAdd(&g_cur[dst[i]], 1);
        g_csr[p] = src[i];
    }
}

// ---------------- node kernel v2: LN + dual GEMM (tf32 tensor cores) + attention dots ----
// Block: 128 rows x 256 cols, 256 threads (8 warps x 32 cols). K=128 in 4 chunks of 32,
// cp.async double-buffered. 2 MMAs per tile (Bhi + Blo split; A single tf32).
#define TMM 128
#define APITCH 132
#define BPITCH 264
#define SM_AS 0
#define SM_BF (128 * APITCH)                 // 16896
#define BKBUF (32 * BPITCH)                  // 8448
#define SM_MU (SM_BF + 4 * BKBUF)            // 50688
#define SM_RS (SM_MU + 128)
#define SM_ATT (SM_RS + 128)
#define SM_G  (SM_ATT + 256)
#define SM_BB (SM_G + 128)
#define SM_BP (SM_BB + 128)
#define NODE2_FLOATS (SM_BP + 128)
#define NODE2_BYTES (NODE2_FLOATS * 4)       // 206336 B

__global__ void __launch_bounds__(256, 1) node_k(
    const float* __restrict__ x, const float* __restrict__ att_src,
    const float* __restrict__ att_dst, const float* __restrict__ bproj, int n)
{
    extern __shared__ float sm[];
    int tid = threadIdx.x;
    int wid = tid >> 5, lane = tid & 31;
    int g = lane >> 2, tig = lane & 3;
    int i0 = blockIdx.x * TMM;
    unsigned smbase = (unsigned)__cvta_generic_to_shared(sm);

    if (tid < 128) {
        sm[SM_ATT + tid]       = att_src[tid];
        sm[SM_ATT + 128 + tid] = att_dst[tid];
        sm[SM_G + tid]  = g_G[tid];
        sm[SM_BB + tid] = g_B[tid];
        sm[SM_BP + tid] = bproj[tid];
    }

    // A fill (row-major tf32) + LayerNorm stats
    for (int rr = 0; rr < 16; rr++) {
        int r = wid * 16 + rr;
        int node = i0 + r;
        float4 v = make_float4(0.f, 0.f, 0.f, 0.f);
        if (node < n) v = *(const float4*)&x[(long)node * 128 + lane * 4];
        float s = v.x + v.y + v.z + v.w;
        float q = v.x * v.x + v.y * v.y + v.z * v.z + v.w * v.w;
        #pragma unroll
        for (int o = 16; o > 0; o >>= 1) {
            s += __shfl_xor_sync(0xFFFFFFFFu, s, o);
            q += __shfl_xor_sync(0xFFFFFFFFu, q, o);
        }
        float mu = s * (1.f / 128.f);
        float var = q * (1.f / 128.f) - mu * mu;
        if (lane == 0) { sm[SM_MU + r] = mu; sm[SM_RS + r] = rsqrtf(var + 1e-5f); }
        float4 t;
        t.x = __uint_as_float(tf32u(v.x));
        t.y = __uint_as_float(tf32u(v.y));
        t.z = __uint_as_float(tf32u(v.z));
        t.w = __uint_as_float(tf32u(v.w));
        *(float4*)&sm[SM_AS + r * APITCH + lane * 4] = t;
    }

    // B chunk loader (cp.async, 32 k-rows x 256 cols, hi+lo)
    auto loadB = [&](int kc, int buf) {
        const float* gh = g_Bhi + kc * 32 * 256;
        const float* gl = g_Blo + kc * 32 * 256;
        unsigned bh = smbase + (SM_BF + (buf * 2 + 0) * BKBUF) * 4;
        unsigned bl = smbase + (SM_BF + (buf * 2 + 1) * BKBUF) * 4;
        #pragma unroll
        for (int u = 0; u < 8; u++) {
            int idx = u * 256 + tid;          // float4 index, 0..2047
            int row = idx >> 6, c4 = idx & 63;
            unsigned so = row * BPITCH * 4 + c4 * 16;
            cpa16(bh + so, gh + row * 256 + c4 * 4);
            cpa16(bl + so, gl + row * 256 + c4 * 4);
        }
        asm volatile("cp.async.commit_group;");
    };
    loadB(0, 0);

    float c[8][4][4];
    #pragma unroll
    for (int a = 0; a < 8; a++)
        #pragma unroll
        for (int b = 0; b < 4; b++)
            #pragma unroll
            for (int d = 0; d < 4; d++) c[a][b][d] = 0.f;

    int colb = wid * 32;

    for (int kc = 0; kc < 4; kc++) {
        if (kc) __syncthreads();                // prev compute done; next buffer free
        if (kc < 3) loadB(kc + 1, (kc + 1) & 1);
        if (kc < 3) asm volatile("cp.async.wait_group 1;");
        else        asm volatile("cp.async.wait_group 0;");
        __syncthreads();

        const float* Bh = &sm[SM_BF + ((kc & 1) * 2 + 0) * BKBUF];
        const float* Bl = &sm[SM_BF + ((kc & 1) * 2 + 1) * BKBUF];
        #pragma unroll
        for (int s = 0; s < 4; s++) {
            int k0 = s * 8;
            unsigned bh[4][2], bl[4][2];
            #pragma unroll
            for (int ni = 0; ni < 4; ni++) {
                int col = colb + ni * 8 + g;
                bh[ni][0] = __float_as_uint(Bh[(k0 + tig) * BPITCH + col]);
                bh[ni][1] = __float_as_uint(Bh[(k0 + tig + 4) * BPITCH + col]);
                bl[ni][0] = __float_as_uint(Bl[(k0 + tig) * BPITCH + col]);
                bl[ni][1] = __float_as_uint(Bl[(k0 + tig + 4) * BPITCH + col]);
            }
            int kg = kc * 32 + k0;
            #pragma unroll
            for (int mi = 0; mi < 8; mi++) {
                const float* Ar  = &sm[SM_AS + (mi * 16 + g) * APITCH + kg];
                const float* Ar8 = Ar + 8 * APITCH;
                unsigned a[4];
                a[0] = __float_as_uint(Ar[tig]);
                a[1] = __float_as_uint(Ar8[tig]);
                a[2] = __float_as_uint(Ar[tig + 4]);
                a[3] = __float_as_uint(Ar8[tig + 4]);
                #pragma unroll
                for (int ni = 0; ni < 4; ni++) {
                    mma1688(c[mi][ni], a, bh[ni]);
                    mma1688(c[mi][ni], a, bl[ni]);
                }
            }
        }
    }

    // Epilogue
    if (wid < 4) {
        int h = wid;
        #pragma unroll
        for (int mi = 0; mi < 8; mi++) {
            #pragma unroll
            for (int hf = 0; hf < 2; hf++) {
                int r = mi * 16 + g + hf * 8;
                int node = i0 + r;
                float mu = sm[SM_MU + r], rs = sm[SM_RS + r];
                float ps = 0.f, pd = 0.f;
                #pragma unroll
                for (int ni = 0; ni < 4; ni++) {
                    #pragma unroll
                    for (int j = 0; j < 2; j++) {
                        int cl = ni * 8 + 2 * tig + j;
                        int cg = colb + cl;
                        float acc = c[mi][ni][hf * 2 + j];
                        float val = rs * (acc - mu * sm[SM_G + cg]) + sm[SM_BB + cg];
                        ps += val * sm[SM_ATT + cg];
                        pd += val * sm[SM_ATT + 128 + cg];
                        if (node < n)
                            g_xwh[(long)node * 128 + cl * 4 + h] = __float2half_rn(val);
                    }
                }
                ps += __shfl_xor_sync(0xFFFFFFFFu, ps, 1);
                ps += __shfl_xor_sync(0xFFFFFFFFu, ps, 2);
                pd += __shfl_xor_sync(0xFFFFFFFFu, pd, 1);
                pd += __shfl_xor_sync(0xFFFFFFFFu, pd, 2);
                if (tig == 0 && node < n) {
                    g_as[node * 4 + h] = ps;
                    g_ad[node * 4 + h] = pd;
                }
            }
        }
    } else {
        #pragma unroll
        for (int mi = 0; mi < 8; mi++) {
            #pragma unroll
            for (int hf = 0; hf < 2; hf++) {
                int r = mi * 16 + g + hf * 8;
                int node = i0 + r;
                if (node >= n) continue;
                #pragma unroll
                for (int ni = 0; ni < 4; ni++) {
                    #pragma unroll
                    for (int j = 0; j < 2; j++) {
                        int cl = ni * 8 + 2 * tig + j;
                        int cid = (wid - 4) * 32 + cl;
                        g_id[(long)node * 128 + cid] = c[mi][ni][hf * 2 + j] + sm[SM_BP + cid];
                    }
                }
            }
        }
    }
}

// ---------------- gather: chunked two-phase softmax aggregate (fp16 values) ----------------
__device__ __forceinline__ float lrelu(float z) { return z > 0.f ? z : 0.2f * z; }

__device__ __forceinline__ float4 ldxw_h(long idx128, int lane) {
    const __half* p = g_xwh + idx128 + lane * 4;
    uint2 u = *(const uint2*)p;
    __half2 h0 = *reinterpret_cast<__half2*>(&u.x);
    __half2 h1 = *reinterpret_cast<__half2*>(&u.y);
    float2 f0 = __half22float2(h0);
    float2 f1 = __half22float2(h1);
    return make_float4(f0.x, f0.y, f1.x, f1.y);
}

__global__ void __launch_bounds__(256) gather_k(const float* __restrict__ bias,
                                                float* __restrict__ out, int n)
{
    __shared__ float4 sq[8][32];
    __shared__ int    ss[8][32];
    int w = threadIdx.x >> 5;
    int lane = threadIdx.x & 31;
    int i = blockIdx.x * 8 + w;
    if (i >= n) return;

    float4 ad  = *(const float4*)&g_ad[i * 4];
    float4 asi = *(const float4*)&g_as[i * 4];
    int beg = g_off[i], end = g_off[i + 1];

    long myb = (long)i * 128;
    float4 xv = ldxw_h(myb, lane);

    float p0 = __expf(lrelu(asi.x + ad.x));
    float p1 = __expf(lrelu(asi.y + ad.y));
    float p2 = __expf(lrelu(asi.z + ad.z));
    float p3 = __expf(lrelu(asi.w + ad.w));
    float d0 = p0, d1 = p1, d2 = p2, d3 = p3;
    float a0 = p0 * xv.x, a1 = p1 * xv.y, a2 = p2 * xv.z, a3 = p3 * xv.w;

    for (int cs = beg; cs < end; cs += 32) {
        int cnt = min(32, end - cs);
        int j = cs + lane;
        if (lane < cnt) {
            int s = __ldg(&g_csr[j]);
            float4 a4 = *(const float4*)&g_as[s * 4];
            float4 q;
            q.x = __expf(lrelu(a4.x + ad.x));
            q.y = __expf(lrelu(a4.y + ad.y));
            q.z = __expf(lrelu(a4.z + ad.z));
            q.w = __expf(lrelu(a4.w + ad.w));
            ss[w][lane] = s;
            sq[w][lane] = q;
        }
        __syncwarp();
        #pragma unroll 4
        for (int t = 0; t < cnt; t++) {
            int st = ss[w][t];
            float4 qt = sq[w][t];
            float4 x4 = ldxw_h((long)st * 128, lane);
            d0 += qt.x; a0 = fmaf(qt.x, x4.x, a0);
            d1 += qt.y; a1 = fmaf(qt.y, x4.y, a1);
            d2 += qt.z; a2 = fmaf(qt.z, x4.z, a2);
            d3 += qt.w; a3 = fmaf(qt.w, x4.w, a3);
        }
        __syncwarp();
    }

    float r0 = a0 / (d0 + 1e-16f);
    float r1 = a1 / (d1 + 1e-16f);
    float r2 = a2 / (d2 + 1e-16f);
    float r3 = a3 / (d3 + 1e-16f);

    long ob = myb + lane;
    out[ob +  0] = fmaxf(g_id[ob +  0] + r0 + __ldg(&bias[lane +  0]), 0.f);
    out[ob + 32] = fmaxf(g_id[ob + 32] + r1 + __ldg(&bias[lane + 32]), 0.f);
    out[ob + 64] = fmaxf(g_id[ob + 64] + r2 + __ldg(&bias[lane + 64]), 0.f);
    out[ob + 96] = fmaxf(g_id[ob + 96] + r3 + __ldg(&bias[lane + 96]), 0.f);
}

// ---------------- launch ----------------
extern "C" void kernel_launch(void* const* d_in, const int* in_sizes, int n_in,
                              void* d_out, int out_size)
{
    const float* x        = (const float*)d_in[0];
    const int*   ei       = (const int*)d_in[1];
    const float* gamma    = (const float*)d_in[2];
    const float* beta     = (const float*)d_in[3];
    const float* Wgat     = (const float*)d_in[4];
    const float* att_src  = (const float*)d_in[5];
    const float* att_dst  = (const float*)d_in[6];
    const float* bias_gat = (const float*)d_in[7];
    const float* Wproj    = (const float*)d_in[8];
    const float* bproj    = (const float*)d_in[9];

    int n = in_sizes[0] / 128;
    int e = in_sizes[1] / 2;
    const int* src = ei;
    const int* dst = ei + e;
    int nb = (n + SCB - 1) / SCB;

    void* curp = nullptr;
    cudaGetSymbolAddress(&curp, g_cur);

    cudaFuncSetAttribute(node_k, cudaFuncAttributeMaxDynamicSharedMemorySize, NODE2_BYTES);

    cudaStream_t s2;
    cudaStreamCreate(&s2);
    cudaEvent_t evFork, evJoin;
    cudaEventCreateWithFlags(&evFork, cudaEventDisableTiming);
    cudaEventCreateWithFlags(&evJoin, cudaEventDisableTiming);

    cudaEventRecord(evFork, 0);
    cudaStreamWaitEvent(s2, evFork, 0);

    // side stream: CSR build
    cudaMemsetAsync(curp, 0, n * sizeof(int), s2);
    hist_k<<<(e + 255) / 256, 256, 0, s2>>>(dst, e);
    bsum_k<<<nb, 256, 0, s2>>>(n);
    bscan_k<<<1, 64, 0, s2>>>(nb);
    scanfin_k<<<nb, 256, 0, s2>>>(n);
    scat_k<<<(e + 255) / 256, 256, 0, s2>>>(src, dst, e);
    cudaEventRecord(evJoin, s2);

    // main stream: GEMM path
    prep_k<<<1, 128>>>(gamma, beta, Wgat);
    prep2_k<<<128, 256>>>(gamma, Wgat, Wproj);
    node_k<<<(n + TMM - 1) / TMM, 256, NODE2_BYTES>>>(x, att_src, att_dst, bproj, n);

    cudaStreamWaitEvent(0, evJoin, 0);
    gather_k<<<(n + 7) / 8, 256>>>(bias_gat, (float*)d_out, n);

    cudaEventDestroy(evFork);
    cudaEventDestroy(evJoin);
    cudaStreamDestroy(s2);
}

// round 8
// speedup vs baseline: 2.2682x; 1.1117x over previous
#include <cuda_runtime.h>
#include <cuda_bf16.h>
#include <cuda_fp16.h>

// Problem constants (fixed-shape problem)
#define MAXN 50176
#define MAXE 800256

// ---------------- scratch ----------------
__device__ __align__(16) __half g_xwh[MAXN * 128]; // xw per node (fp16), layout [node][cc*4+h]
__device__ __align__(16) float g_id[MAXN * 128];   // identity = x@W_proj + b_proj, layout [node][c]
__device__ __align__(16) float g_as[MAXN * 4];
__device__ __align__(16) float g_ad[MAXN * 4];
__device__ __align__(16) int   g_cur[MAXN];
__device__ int   g_off[MAXN + 1];
__device__ int   g_csr[MAXE];
__device__ int   g_bsum[64];
__device__ float g_G[128];                          // colsum of gamma*W_gat
__device__ float g_B[128];                          // beta @ W_gat
__device__ __align__(16) float g_Bhi[128 * 256];    // tf32 of [gamma*Wgat | Wproj], [k][c]

// ---------------- tf32 / mma helpers ----------------
__device__ __forceinline__ unsigned tf32u(float x) {
    unsigned r; asm("cvt.rna.tf32.f32 %0, %1;" : "=r"(r) : "f"(x)); return r;
}
__device__ __forceinline__ void mma1688(float* c, const unsigned* a, const unsigned* b) {
    asm volatile("mma.sync.aligned.m16n8k8.row.col.f32.tf32.tf32.f32 "
        "{%0,%1,%2,%3},{%4,%5,%6,%7},{%8,%9},{%0,%1,%2,%3};"
        : "+f"(c[0]), "+f"(c[1]), "+f"(c[2]), "+f"(c[3])
        : "r"(a[0]), "r"(a[1]), "r"(a[2]), "r"(a[3]), "r"(b[0]), "r"(b[1]));
}
__device__ __forceinline__ void cpa16(unsigned s, const float* g) {
    asm volatile("cp.async.ca.shared.global [%0], [%1], 16;" :: "r"(s), "l"(g));
}

// ---------------- prep: G, B colsums ----------------
__global__ void prep_k(const float* __restrict__ gamma, const float* __restrict__ beta,
                       const float* __restrict__ Wgat) {
    int c = threadIdx.x;
    if (c < 128) {
        float G = 0.f, B = 0.f;
        for (int k = 0; k < 128; k++) {
            float w = Wgat[k * 128 + c];
            G += gamma[k] * w;
            B += beta[k] * w;
        }
        g_G[c] = G;
        g_B[c] = B;
    }
}

// prep2: tf32 round of the fused weight matrix [gamma*Wgat | Wproj]
__global__ void prep2_k(const float* __restrict__ gamma, const float* __restrict__ Wgat,
                        const float* __restrict__ Wproj) {
    int k = blockIdx.x;          // 0..127
    int c = threadIdx.x;         // 0..255
    float w;
    if (c < 128) w = gamma[k] * Wgat[k * 128 + c];
    else         w = Wproj[k * 128 + (c - 128)];
    g_Bhi[k * 256 + c] = __uint_as_float(tf32u(w));
}

// ---------------- CSR build ----------------
__global__ void hist_k(const int* __restrict__ dst, int e) {
    int i = blockIdx.x * blockDim.x + threadIdx.x;
    if (i < e) atomicAdd(&g_cur[dst[i]], 1);
}

#define SCB 1024
__global__ void bsum_k(int n) {
    __shared__ int wsum[8];
    int b = blockIdx.x, tid = threadIdx.x, lane = tid & 31, wid = tid >> 5;
    int base = b * SCB + tid * 4;
    int4 v = make_int4(0, 0, 0, 0);
    if (base + 3 < n)      v = *(const int4*)&g_cur[base];
    else {
        if (base     < n) v.x = g_cur[base];
        if (base + 1 < n) v.y = g_cur[base + 1];
        if (base + 2 < n) v.z = g_cur[base + 2];
    }
    int s = v.x + v.y + v.z + v.w;
    #pragma unroll
    for (int o = 16; o > 0; o >>= 1) s += __shfl_xor_sync(0xFFFFFFFFu, s, o);
    if (lane == 0) wsum[wid] = s;
    __syncthreads();
    if (wid == 0 && lane < 8) {
        int t = wsum[lane];
        #pragma unroll
        for (int o = 4; o > 0; o >>= 1) t += __shfl_xor_sync(0xFFu, t, o);
        if (lane == 0) g_bsum[b] = t;
    }
}

__global__ void bscan_k(int nb) {
    __shared__ int w0tot;
    int tid = threadIdx.x, lane = tid & 31, wid = tid >> 5;
    int v = (tid < nb) ? g_bsum[tid] : 0;
    int inc = v;
    #pragma unroll
    for (int o = 1; o < 32; o <<= 1) {
        int t = __shfl_up_sync(0xFFFFFFFFu, inc, o);
        if (lane >= o) inc += t;
    }
    if (wid == 0 && lane == 31) w0tot = inc;
    __syncthreads();
    int ex = inc - v + (wid == 1 ? w0tot : 0);
    if (tid < nb) g_bsum[tid] = ex;
}

__global__ void scanfin_k(int n) {
    __shared__ int wsum[8];
    int b = blockIdx.x, tid = threadIdx.x, lane = tid & 31, wid = tid >> 5;
    int base = b * SCB + tid * 4;
    int4 v = make_int4(0, 0, 0, 0);
    if (base + 3 < n)      v = *(const int4*)&g_cur[base];
    else {
        if (base     < n) v.x = g_cur[base];
        if (base + 1 < n) v.y = g_cur[base + 1];
        if (base + 2 < n) v.z = g_cur[base + 2];
    }
    int tsum = v.x + v.y + v.z + v.w;
    int inc = tsum;
    #pragma unroll
    for (int o = 1; o < 32; o <<= 1) {
        int t = __shfl_up_sync(0xFFFFFFFFu, inc, o);
        if (lane >= o) inc += t;
    }
    if (lane == 31) wsum[wid] = inc;
    __syncthreads();
    if (wid == 0 && lane < 8) {
        int wv = wsum[lane];
        int wi = wv;
        #pragma unroll
        for (int o = 1; o < 8; o <<= 1) {
            int t = __shfl_up_sync(0xFFu, wi, o);
            if (lane >= o) wi += t;
        }
        wsum[lane] = wi - wv;
    }
    __syncthreads();
    int e0 = inc - tsum + wsum[wid] + g_bsum[b];
    int e1 = e0 + v.x, e2 = e1 + v.y, e3 = e2 + v.z, e4 = e3 + v.w;
    if (base     < n) { g_cur[base]     = e0; g_off[base + 1] = e1; }
    if (base + 1 < n) { g_cur[base + 1] = e1; g_off[base + 2] = e2; }
    if (base + 2 < n) { g_cur[base + 2] = e2; g_off[base + 3] = e3; }
    if (base + 3 < n) { g_cur[base + 3] = e3; g_off[base + 4] = e4; }
    if (b == 0 && tid == 0) g_off[0] = 0;
}

__global__ void scat_k(const int* __restrict__ src, const int* __restrict__ dst, int e) {
    int i = blockIdx.x * blockDim.x + threadIdx.x;
    if (i < e) {
        int p = atomicAdd(&g_cur[dst[i]], 1);
        g_csr[p] = src[i];
    }
}

// ---------------- node kernel: LN + dual GEMM (single-tf32 tensor cores) + attn dots ----
// Block: 128 rows x 256 cols, 256 threads (8 warps x 32 cols). K=128 in 4 chunks of 32,
// cp.async double-buffered. 1 MMA per tile (single tf32 A and B).
#define TMM 128
#define APITCH 132
#define BPITCH 264
#define SM_AS 0
#define SM_BF (128 * APITCH)                 // 16896
#define BKBUF (32 * BPITCH)                  // 8448
#define SM_MU (SM_BF + 2 * BKBUF)            // 33792
#define SM_RS (SM_MU + 128)
#define SM_ATT (SM_RS + 128)
#define SM_G  (SM_ATT + 256)
#define SM_BB (SM_G + 128)
#define SM_BP (SM_BB + 128)
#define NODE2_FLOATS (SM_BP + 128)
#define NODE2_BYTES (NODE2_FLOATS * 4)       // ~138 KB

__global__ void __launch_bounds__(256, 1) node_k(
    const float* __restrict__ x, const float* __restrict__ att_src,
    const float* __restrict__ att_dst, const float* __restrict__ bproj, int n)
{
    extern __shared__ float sm[];
    int tid = threadIdx.x;
    int wid = tid >> 5, lane = tid & 31;
    int g = lane >> 2, tig = lane & 3;
    int i0 = blockIdx.x * TMM;
    unsigned smbase = (unsigned)__cvta_generic_to_shared(sm);

    if (tid < 128) {
        sm[SM_ATT + tid]       = att_src[tid];
        sm[SM_ATT + 128 + tid] = att_dst[tid];
        sm[SM_G + tid]  = g_G[tid];
        sm[SM_BB + tid] = g_B[tid];
        sm[SM_BP + tid] = bproj[tid];
    }

    // B chunk loader (cp.async, 32 k-rows x 256 cols)
    auto loadB = [&](int kc, int buf) {
        const float* gh = g_Bhi + kc * 32 * 256;
        unsigned bh = smbase + (SM_BF + buf * BKBUF) * 4;
        #pragma unroll
        for (int u = 0; u < 8; u++) {
            int idx = u * 256 + tid;          // float4 index, 0..2047
            int row = idx >> 6, c4 = idx & 63;
            cpa16(bh + row * BPITCH * 4 + c4 * 16, gh + row * 256 + c4 * 4);
        }
        asm volatile("cp.async.commit_group;");
    };
    loadB(0, 0);

    // A fill (row-major tf32) + LayerNorm stats
    for (int rr = 0; rr < 16; rr++) {
        int r = wid * 16 + rr;
        int node = i0 + r;
        float4 v = make_float4(0.f, 0.f, 0.f, 0.f);
        if (node < n) v = *(const float4*)&x[(long)node * 128 + lane * 4];
        float s = v.x + v.y + v.z + v.w;
        float q = v.x * v.x + v.y * v.y + v.z * v.z + v.w * v.w;
        #pragma unroll
        for (int o = 16; o > 0; o >>= 1) {
            s += __shfl_xor_sync(0xFFFFFFFFu, s, o);
            q += __shfl_xor_sync(0xFFFFFFFFu, q, o);
        }
        float mu = s * (1.f / 128.f);
        float var = q * (1.f / 128.f) - mu * mu;
        if (lane == 0) { sm[SM_MU + r] = mu; sm[SM_RS + r] = rsqrtf(var + 1e-5f); }
        float4 t;
        t.x = __uint_as_float(tf32u(v.x));
        t.y = __uint_as_float(tf32u(v.y));
        t.z = __uint_as_float(tf32u(v.z));
        t.w = __uint_as_float(tf32u(v.w));
        *(float4*)&sm[SM_AS + r * APITCH + lane * 4] = t;
    }

    float c[8][4][4];
    #pragma unroll
    for (int a = 0; a < 8; a++)
        #pragma unroll
        for (int b = 0; b < 4; b++)
            #pragma unroll
            for (int d = 0; d < 4; d++) c[a][b][d] = 0.f;

    int colb = wid * 32;

    for (int kc = 0; kc < 4; kc++) {
        if (kc) __syncthreads();
        if (kc < 3) loadB(kc + 1, (kc + 1) & 1);
        if (kc < 3) asm volatile("cp.async.wait_group 1;");
        else        asm volatile("cp.async.wait_group 0;");
        __syncthreads();

        const float* Bh = &sm[SM_BF + (kc & 1) * BKBUF];
        #pragma unroll
        for (int s = 0; s < 4; s++) {
            int k0 = s * 8;
            unsigned bh[4][2];
            #pragma unroll
            for (int ni = 0; ni < 4; ni++) {
                int col = colb + ni * 8 + g;
                bh[ni][0] = __float_as_uint(Bh[(k0 + tig) * BPITCH + col]);
                bh[ni][1] = __float_as_uint(Bh[(k0 + tig + 4) * BPITCH + col]);
            }
            int kg = kc * 32 + k0;
            #pragma unroll
            for (int mi = 0; mi < 8; mi++) {
                const float* Ar  = &sm[SM_AS + (mi * 16 + g) * APITCH + kg];
                const float* Ar8 = Ar + 8 * APITCH;
                unsigned a[4];
                a[0] = __float_as_uint(Ar[tig]);
                a[1] = __float_as_uint(Ar8[tig]);
                a[2] = __float_as_uint(Ar[tig + 4]);
                a[3] = __float_as_uint(Ar8[tig + 4]);
                #pragma unroll
                for (int ni = 0; ni < 4; ni++)
                    mma1688(c[mi][ni], a, bh[ni]);
            }
        }
    }

    // Epilogue
    if (wid < 4) {
        int h = wid;
        #pragma unroll
        for (int mi = 0; mi < 8; mi++) {
            #pragma unroll
            for (int hf = 0; hf < 2; hf++) {
                int r = mi * 16 + g + hf * 8;
                int node = i0 + r;
                float mu = sm[SM_MU + r], rs = sm[SM_RS + r];
                float ps = 0.f, pd = 0.f;
                #pragma unroll
                for (int ni = 0; ni < 4; ni++) {
                    #pragma unroll
                    for (int j = 0; j < 2; j++) {
                        int cl = ni * 8 + 2 * tig + j;
                        int cg = colb + cl;
                        float acc = c[mi][ni][hf * 2 + j];
                        float val = rs * (acc - mu * sm[SM_G + cg]) + sm[SM_BB + cg];
                        ps += val * sm[SM_ATT + cg];
                        pd += val * sm[SM_ATT + 128 + cg];
                        if (node < n)
                            g_xwh[(long)node * 128 + cl * 4 + h] = __float2half_rn(val);
                    }
                }
                ps += __shfl_xor_sync(0xFFFFFFFFu, ps, 1);
                ps += __shfl_xor_sync(0xFFFFFFFFu, ps, 2);
                pd += __shfl_xor_sync(0xFFFFFFFFu, pd, 1);
                pd += __shfl_xor_sync(0xFFFFFFFFu, pd, 2);
                if (tig == 0 && node < n) {
                    g_as[node * 4 + h] = ps;
                    g_ad[node * 4 + h] = pd;
                }
            }
        }
    } else {
        #pragma unroll
        for (int mi = 0; mi < 8; mi++) {
            #pragma unroll
            for (int hf = 0; hf < 2; hf++) {
                int r = mi * 16 + g + hf * 8;
                int node = i0 + r;
                if (node >= n) continue;
                #pragma unroll
                for (int ni = 0; ni < 4; ni++) {
                    #pragma unroll
                    for (int j = 0; j < 2; j++) {
                        int cl = ni * 8 + 2 * tig + j;
                        int cid = (wid - 4) * 32 + cl;
                        g_id[(long)node * 128 + cid] = c[mi][ni][hf * 2 + j] + sm[SM_BP + cid];
                    }
                }
            }
        }
    }
}

// ---------------- gather: chunked two-phase softmax aggregate (fp16 values) ----------------
__device__ __forceinline__ float lrelu(float z) { return z > 0.f ? z : 0.2f * z; }

__device__ __forceinline__ float4 ldxw_h(long idx128, int lane) {
    const __half* p = g_xwh + idx128 + lane * 4;
    uint2 u = *(const uint2*)p;
    __half2 h0 = *reinterpret_cast<__half2*>(&u.x);
    __half2 h1 = *reinterpret_cast<__half2*>(&u.y);
    float2 f0 = __half22float2(h0);
    float2 f1 = __half22float2(h1);
    return make_float4(f0.x, f0.y, f1.x, f1.y);
}

__global__ void __launch_bounds__(256) gather_k(const float* __restrict__ bias,
                                                float* __restrict__ out, int n)
{
    __shared__ float4 sq[8][32];
    __shared__ int    ss[8][32];
    int w = threadIdx.x >> 5;
    int lane = threadIdx.x & 31;
    int i = blockIdx.x * 8 + w;
    if (i >= n) return;

    float4 ad  = *(const float4*)&g_ad[i * 4];
    float4 asi = *(const float4*)&g_as[i * 4];
    int beg = g_off[i], end = g_off[i + 1];

    long myb = (long)i * 128;
    float4 xv = ldxw_h(myb, lane);

    float p0 = __expf(lrelu(asi.x + ad.x));
    float p1 = __expf(lrelu(asi.y + ad.y));
    float p2 = __expf(lrelu(asi.z + ad.z));
    float p3 = __expf(lrelu(asi.w + ad.w));
    float d0 = p0, d1 = p1, d2 = p2, d3 = p3;
    float a0 = p0 * xv.x, a1 = p1 * xv.y, a2 = p2 * xv.z, a3 = p3 * xv.w;

    for (int cs = beg; cs < end; cs += 32) {
        int cnt = min(32, end - cs);
        int j = cs + lane;
        if (lane < cnt) {
            int s = __ldg(&g_csr[j]);
            float4 a4 = *(const float4*)&g_as[s * 4];
            float4 q;
            q.x = __expf(lrelu(a4.x + ad.x));
            q.y = __expf(lrelu(a4.y + ad.y));
            q.z = __expf(lrelu(a4.z + ad.z));
            q.w = __expf(lrelu(a4.w + ad.w));
            ss[w][lane] = s;
            sq[w][lane] = q;
        }
        __syncwarp();
        #pragma unroll 4
        for (int t = 0; t < cnt; t++) {
            int st = ss[w][t];
            float4 qt = sq[w][t];
            float4 x4 = ldxw_h((long)st * 128, lane);
            d0 += qt.x; a0 = fmaf(qt.x, x4.x, a0);
            d1 += qt.y; a1 = fmaf(qt.y, x4.y, a1);
            d2 += qt.z; a2 = fmaf(qt.z, x4.z, a2);
            d3 += qt.w; a3 = fmaf(qt.w, x4.w, a3);
        }
        __syncwarp();
    }

    float r0 = a0 / (d0 + 1e-16f);
    float r1 = a1 / (d1 + 1e-16f);
    float r2 = a2 / (d2 + 1e-16f);
    float r3 = a3 / (d3 + 1e-16f);

    long ob = myb + lane;
    out[ob +  0] = fmaxf(g_id[ob +  0] + r0 + __ldg(&bias[lane +  0]), 0.f);
    out[ob + 32] = fmaxf(g_id[ob + 32] + r1 + __ldg(&bias[lane + 32]), 0.f);
    out[ob + 64] = fmaxf(g_id[ob + 64] + r2 + __ldg(&bias[lane + 64]), 0.f);
    out[ob + 96] = fmaxf(g_id[ob + 96] + r3 + __ldg(&bias[lane + 96]), 0.f);
}

// ---------------- launch ----------------
extern "C" void kernel_launch(void* const* d_in, const int* in_sizes, int n_in,
                              void* d_out, int out_size)
{
    const float* x        = (const float*)d_in[0];
    const int*   ei       = (const int*)d_in[1];
    const float* gamma    = (const float*)d_in[2];
    const float* beta     = (const float*)d_in[3];
    const float* Wgat     = (const float*)d_in[4];
    const float* att_src  = (const float*)d_in[5];
    const float* att_dst  = (const float*)d_in[6];
    const float* bias_gat = (const float*)d_in[7];
    const float* Wproj    = (const float*)d_in[8];
    const float* bproj    = (const float*)d_in[9];

    int n = in_sizes[0] / 128;
    int e = in_sizes[1] / 2;
    const int* src = ei;
    const int* dst = ei + e;
    int nb = (n + SCB - 1) / SCB;

    void* curp = nullptr;
    cudaGetSymbolAddress(&curp, g_cur);

    cudaFuncSetAttribute(node_k, cudaFuncAttributeMaxDynamicSharedMemorySize, NODE2_BYTES);

    cudaStream_t s2;
    cudaStreamCreate(&s2);
    cudaEvent_t evFork, evJoin;
    cudaEventCreateWithFlags(&evFork, cudaEventDisableTiming);
    cudaEventCreateWithFlags(&evJoin, cudaEventDisableTiming);

    cudaEventRecord(evFork, 0);
    cudaStreamWaitEvent(s2, evFork, 0);

    // side stream: CSR build
    cudaMemsetAsync(curp, 0, n * sizeof(int), s2);
    hist_k<<<(e + 255) / 256, 256, 0, s2>>>(dst, e);
    bsum_k<<<nb, 256, 0, s2>>>(n);
    bscan_k<<<1, 64, 0, s2>>>(nb);
    scanfin_k<<<nb, 256, 0, s2>>>(n);
    scat_k<<<(e + 255) / 256, 256, 0, s2>>>(src, dst, e);
    cudaEventRecord(evJoin, s2);

    // main stream: GEMM path
    prep_k<<<1, 128>>>(gamma, beta, Wgat);
    prep2_k<<<128, 256>>>(gamma, Wgat, Wproj);
    node_k<<<(n + TMM - 1) / TMM, 256, NODE2_BYTES>>>(x, att_src, att_dst, bproj, n);

    cudaStreamWaitEvent(0, evJoin, 0);
    gather_k<<<(n + 7) / 8, 256>>>(bias_gat, (float*)d_out, n);

    cudaEventDestroy(evFork);
    cudaEventDestroy(evJoin);
    cudaStreamDestroy(s2);
}

// round 9
// speedup vs baseline: 2.5508x; 1.1246x over previous
#include <cuda_runtime.h>
#include <cuda_bf16.h>
#include <cuda_fp16.h>

// Problem constants (fixed-shape problem)
#define MAXN 50176
#define MAXE 800256

// ---------------- scratch ----------------
__device__ __align__(16) __half g_xwh[MAXN * 128]; // xw per node (fp16), layout [node][cc*4+h]
__device__ __align__(16) float g_id[MAXN * 128];   // identity = x@W_proj + b_proj, layout [node][c]
__device__ __align__(16) float g_as[MAXN * 4];
__device__ __align__(16) float g_ad[MAXN * 4];
__device__ __align__(16) int   g_cur[MAXN];
__device__ int   g_off[MAXN + 1];
__device__ int   g_csr[MAXE];
__device__ int   g_bsum[64];
__device__ float g_G[128];                          // colsum of tf32(gamma*W_gat)
__device__ float g_B[128];                          // beta @ W_gat
__device__ __align__(16) float g_Bp[256 * 128];     // tf32 fused weights TRANSPOSED: [c][k]

// ---------------- tf32 / mma helpers ----------------
__device__ __forceinline__ unsigned tf32u(float x) {
    unsigned r; asm("cvt.rna.tf32.f32 %0, %1;" : "=r"(r) : "f"(x)); return r;
}
__device__ __forceinline__ void mma1688(float* c, const unsigned* a, const unsigned* b) {
    asm volatile("mma.sync.aligned.m16n8k8.row.col.f32.tf32.tf32.f32 "
        "{%0,%1,%2,%3},{%4,%5,%6,%7},{%8,%9},{%0,%1,%2,%3};"
        : "+f"(c[0]), "+f"(c[1]), "+f"(c[2]), "+f"(c[3])
        : "r"(a[0]), "r"(a[1]), "r"(a[2]), "r"(a[3]), "r"(b[0]), "r"(b[1]));
}
__device__ __forceinline__ void cpa16(unsigned s, const float* g) {
    asm volatile("cp.async.ca.shared.global [%0], [%1], 16;" :: "r"(s), "l"(g));
}

// ---------------- prep (merged): tf32 weights transposed + G/B colsums ----------------
// grid 256 blocks (one per output col c), 128 threads (k).
__global__ void prep2_k(const float* __restrict__ gamma, const float* __restrict__ beta,
                        const float* __restrict__ Wgat, const float* __restrict__ Wproj) {
    __shared__ float s1[4], s2[4];
    int c = blockIdx.x, k = threadIdx.x;
    int lane = k & 31, wid = k >> 5;
    float w;
    if (c < 128) w = gamma[k] * Wgat[k * 128 + c];
    else         w = Wproj[k * 128 + (c - 128)];
    float wr = __uint_as_float(tf32u(w));
    g_Bp[c * 128 + k] = wr;
    if (c < 128) {
        float sw = wr;
        float sb = beta[k] * Wgat[k * 128 + c];
        #pragma unroll
        for (int o = 16; o > 0; o >>= 1) {
            sw += __shfl_xor_sync(0xFFFFFFFFu, sw, o);
            sb += __shfl_xor_sync(0xFFFFFFFFu, sb, o);
        }
        if (lane == 0) { s1[wid] = sw; s2[wid] = sb; }
        __syncthreads();
        if (k == 0) {
            g_G[c] = s1[0] + s1[1] + s1[2] + s1[3];
            g_B[c] = s2[0] + s2[1] + s2[2] + s2[3];
        }
    }
}

// ---------------- CSR build ----------------
__global__ void hist_k(const int* __restrict__ dst, int e) {
    int i = blockIdx.x * blockDim.x + threadIdx.x;
    if (i < e) atomicAdd(&g_cur[dst[i]], 1);
}

#define SCB 1024
__global__ void bsum_k(int n) {
    __shared__ int wsum[8];
    int b = blockIdx.x, tid = threadIdx.x, lane = tid & 31, wid = tid >> 5;
    int base = b * SCB + tid * 4;
    int4 v = make_int4(0, 0, 0, 0);
    if (base + 3 < n)      v = *(const int4*)&g_cur[base];
    else {
        if (base     < n) v.x = g_cur[base];
        if (base + 1 < n) v.y = g_cur[base + 1];
        if (base + 2 < n) v.z = g_cur[base + 2];
    }
    int s = v.x + v.y + v.z + v.w;
    #pragma unroll
    for (int o = 16; o > 0; o >>= 1) s += __shfl_xor_sync(0xFFFFFFFFu, s, o);
    if (lane == 0) wsum[wid] = s;
    __syncthreads();
    if (wid == 0 && lane < 8) {
        int t = wsum[lane];
        #pragma unroll
        for (int o = 4; o > 0; o >>= 1) t += __shfl_xor_sync(0xFFu, t, o);
        if (lane == 0) g_bsum[b] = t;
    }
}

__global__ void bscan_k(int nb) {
    __shared__ int w0tot;
    int tid = threadIdx.x, lane = tid & 31, wid = tid >> 5;
    int v = (tid < nb) ? g_bsum[tid] : 0;
    int inc = v;
    #pragma unroll
    for (int o = 1; o < 32; o <<= 1) {
        int t = __shfl_up_sync(0xFFFFFFFFu, inc, o);
        if (lane >= o) inc += t;
    }
    if (wid == 0 && lane == 31) w0tot = inc;
    __syncthreads();
    int ex = inc - v + (wid == 1 ? w0tot : 0);
    if (tid < nb) g_bsum[tid] = ex;
}

__global__ void scanfin_k(int n) {
    __shared__ int wsum[8];
    int b = blockIdx.x, tid = threadIdx.x, lane = tid & 31, wid = tid >> 5;
    int base = b * SCB + tid * 4;
    int4 v = make_int4(0, 0, 0, 0);
    if (base + 3 < n)      v = *(const int4*)&g_cur[base];
    else {
        if (base     < n) v.x = g_cur[base];
        if (base + 1 < n) v.y = g_cur[base + 1];
        if (base + 2 < n) v.z = g_cur[base + 2];
    }
    int tsum = v.x + v.y + v.z + v.w;
    int inc = tsum;
    #pragma unroll
    for (int o = 1; o < 32; o <<= 1) {
        int t = __shfl_up_sync(0xFFFFFFFFu, inc, o);
        if (lane >= o) inc += t;
    }
    if (lane == 31) wsum[wid] = inc;
    __syncthreads();
    if (wid == 0 && lane < 8) {
        int wv = wsum[lane];
        int wi = wv;
        #pragma unroll
        for (int o = 1; o < 8; o <<= 1) {
            int t = __shfl_up_sync(0xFFu, wi, o);
            if (lane >= o) wi += t;
        }
        wsum[lane] = wi - wv;
    }
    __syncthreads();
    int e0 = inc - tsum + wsum[wid] + g_bsum[b];
    int e1 = e0 + v.x, e2 = e1 + v.y, e3 = e2 + v.z, e4 = e3 + v.w;
    if (base     < n) { g_cur[base]     = e0; g_off[base + 1] = e1; }
    if (base + 1 < n) { g_cur[base + 1] = e1; g_off[base + 2] = e2; }
    if (base + 2 < n) { g_cur[base + 2] = e2; g_off[base + 3] = e3; }
    if (base + 3 < n) { g_cur[base + 3] = e3; g_off[base + 4] = e4; }
    if (b == 0 && tid == 0) g_off[0] = 0;
}

__global__ void scat_k(const int* __restrict__ src, const int* __restrict__ dst, int e) {
    int i = blockIdx.x * blockDim.x + threadIdx.x;
    if (i < e) {
        int p = atomicAdd(&g_cur[dst[i]], 1);
        g_csr[p] = src[i];
    }
}

// ---------------- node kernel: LN + dual GEMM (tf32, vectorized frags) + attn dots ----
// k-relabeling: logical slot (kc,s,tig,half) <-> physical k = kc*32 + tig*8 + 2s + half.
// A stored row-major natural; B stored [c][k]; all fragment loads are LDS.128.
#define TMM 128
#define APITCH 132
#define BKP 36                               // smem pitch per col (32 k-floats + pad)
#define SM_AS 0
#define SM_BF (128 * APITCH)                 // 16896
#define BKBUF (256 * BKP)                    // 9216 floats per buffer
#define SM_MU (SM_BF + 2 * BKBUF)            // 35328
#define SM_RS (SM_MU + 128)
#define SM_ATT (SM_RS + 128)
#define SM_G  (SM_ATT + 256)
#define SM_BB (SM_G + 128)
#define SM_BP (SM_BB + 128)
#define NODE2_FLOATS (SM_BP + 128)
#define NODE2_BYTES (NODE2_FLOATS * 4)       // ~145 KB

__global__ void __launch_bounds__(256, 1) node_k(
    const float* __restrict__ x, const float* __restrict__ att_src,
    const float* __restrict__ att_dst, const float* __restrict__ bproj, int n)
{
    extern __shared__ float sm[];
    int tid = threadIdx.x;
    int wid = tid >> 5, lane = tid & 31;
    int g = lane >> 2, tig = lane & 3;
    int i0 = blockIdx.x * TMM;
    unsigned smbase = (unsigned)__cvta_generic_to_shared(sm);

    if (tid < 128) {
        sm[SM_ATT + tid]       = att_src[tid];
        sm[SM_ATT + 128 + tid] = att_dst[tid];
        sm[SM_G + tid]  = g_G[tid];
        sm[SM_BB + tid] = g_B[tid];
        sm[SM_BP + tid] = bproj[tid];
    }

    // B chunk loader: for chunk kc copy Bp[c][kc*32 .. +31] -> Bs[c*BKP .. +31]
    auto loadB = [&](int kc, int buf) {
        const float* gp = g_Bp + kc * 32;
        unsigned bs = smbase + (SM_BF + buf * BKBUF) * 4;
        #pragma unroll
        for (int u = 0; u < 8; u++) {
            int idx = u * 256 + tid;          // 0..2047
            int c = idx >> 3, q = idx & 7;    // q = float4 quad within 32
            cpa16(bs + (c * BKP + q * 4) * 4, gp + c * 128 + q * 4);
        }
        asm volatile("cp.async.commit_group;");
    };
    loadB(0, 0);

    // A fill (row-major tf32) + LayerNorm stats
    for (int rr = 0; rr < 16; rr++) {
        int r = wid * 16 + rr;
        int node = i0 + r;
        float4 v = make_float4(0.f, 0.f, 0.f, 0.f);
        if (node < n) v = *(const float4*)&x[(long)node * 128 + lane * 4];
        float s = v.x + v.y + v.z + v.w;
        float q = v.x * v.x + v.y * v.y + v.z * v.z + v.w * v.w;
        #pragma unroll
        for (int o = 16; o > 0; o >>= 1) {
            s += __shfl_xor_sync(0xFFFFFFFFu, s, o);
            q += __shfl_xor_sync(0xFFFFFFFFu, q, o);
        }
        float mu = s * (1.f / 128.f);
        float var = q * (1.f / 128.f) - mu * mu;
        if (lane == 0) { sm[SM_MU + r] = mu; sm[SM_RS + r] = rsqrtf(var + 1e-5f); }
        float4 t;
        t.x = __uint_as_float(tf32u(v.x));
        t.y = __uint_as_float(tf32u(v.y));
        t.z = __uint_as_float(tf32u(v.z));
        t.w = __uint_as_float(tf32u(v.w));
        *(float4*)&sm[SM_AS + r * APITCH + lane * 4] = t;
    }

    float c[8][4][4];
    #pragma unroll
    for (int a = 0; a < 8; a++)
        #pragma unroll
        for (int b = 0; b < 4; b++)
            #pragma unroll
            for (int d = 0; d < 4; d++) c[a][b][d] = 0.f;

    int colb = wid * 32;

    for (int kc = 0; kc < 4; kc++) {
        if (kc) __syncthreads();
        if (kc < 3) loadB(kc + 1, (kc + 1) & 1);
        if (kc < 3) asm volatile("cp.async.wait_group 1;");
        else        asm volatile("cp.async.wait_group 0;");
        __syncthreads();

        const float* Bh = &sm[SM_BF + (kc & 1) * BKBUF];

        // B frags: per ni, 8 contiguous k-floats (tig*8 .. +7) -> 2x LDS.128
        float4 bf[4][2];
        #pragma unroll
        for (int ni = 0; ni < 4; ni++) {
            int col = colb + ni * 8 + g;
            const float* bp = &Bh[col * BKP + tig * 8];
            bf[ni][0] = *(const float4*)bp;
            bf[ni][1] = *(const float4*)(bp + 4);
        }

        #pragma unroll
        for (int mi = 0; mi < 8; mi++) {
            const float* Ar = &sm[SM_AS + (mi * 16 + g) * APITCH + kc * 32 + tig * 8];
            const float* Ar8 = Ar + 8 * APITCH;
            float4 a0 = *(const float4*)Ar;
            float4 a1 = *(const float4*)(Ar + 4);
            float4 e0 = *(const float4*)Ar8;
            float4 e1 = *(const float4*)(Ar8 + 4);
            unsigned a[4]; unsigned b[2];
            // s=0: k-pair (0,1) of this thread's 8
            a[0] = __float_as_uint(a0.x); a[1] = __float_as_uint(e0.x);
            a[2] = __float_as_uint(a0.y); a[3] = __float_as_uint(e0.y);
            #pragma unroll
            for (int ni = 0; ni < 4; ni++) {
                b[0] = __float_as_uint(bf[ni][0].x); b[1] = __float_as_uint(bf[ni][0].y);
                mma1688(c[mi][ni], a, b);
            }
            // s=1
            a[0] = __float_as_uint(a0.z); a[1] = __float_as_uint(e0.z);
            a[2] = __float_as_uint(a0.w); a[3] = __float_as_uint(e0.w);
            #pragma unroll
            for (int ni = 0; ni < 4; ni++) {
                b[0] = __float_as_uint(bf[ni][0].z); b[1] = __float_as_uint(bf[ni][0].w);
                mma1688(c[mi][ni], a, b);
            }
            // s=2
            a[0] = __float_as_uint(a1.x); a[1] = __float_as_uint(e1.x);
            a[2] = __float_as_uint(a1.y); a[3] = __float_as_uint(e1.y);
            #pragma unroll
            for (int ni = 0; ni < 4; ni++) {
                b[0] = __float_as_uint(bf[ni][1].x); b[1] = __float_as_uint(bf[ni][1].y);
                mma1688(c[mi][ni], a, b);
            }
            // s=3
            a[0] = __float_as_uint(a1.z); a[1] = __float_as_uint(e1.z);
            a[2] = __float_as_uint(a1.w); a[3] = __float_as_uint(e1.w);
            #pragma unroll
            for (int ni = 0; ni < 4; ni++) {
                b[0] = __float_as_uint(bf[ni][1].z); b[1] = __float_as_uint(bf[ni][1].w);
                mma1688(c[mi][ni], a, b);
            }
        }
    }

    // Epilogue
    if (wid < 4) {
        int h = wid;
        #pragma unroll
        for (int mi = 0; mi < 8; mi++) {
            #pragma unroll
            for (int hf = 0; hf < 2; hf++) {
                int r = mi * 16 + g + hf * 8;
                int node = i0 + r;
                float mu = sm[SM_MU + r], rs = sm[SM_RS + r];
                float ps = 0.f, pd = 0.f;
                #pragma unroll
                for (int ni = 0; ni < 4; ni++) {
                    #pragma unroll
                    for (int j = 0; j < 2; j++) {
                        int cl = ni * 8 + 2 * tig + j;
                        int cg = colb + cl;
                        float acc = c[mi][ni][hf * 2 + j];
                        float val = rs * (acc - mu * sm[SM_G + cg]) + sm[SM_BB + cg];
                        ps += val * sm[SM_ATT + cg];
                        pd += val * sm[SM_ATT + 128 + cg];
                        if (node < n)
                            g_xwh[(long)node * 128 + cl * 4 + h] = __float2half_rn(val);
                    }
                }
                ps += __shfl_xor_sync(0xFFFFFFFFu, ps, 1);
                ps += __shfl_xor_sync(0xFFFFFFFFu, ps, 2);
                pd += __shfl_xor_sync(0xFFFFFFFFu, pd, 1);
                pd += __shfl_xor_sync(0xFFFFFFFFu, pd, 2);
                if (tig == 0 && node < n) {
                    g_as[node * 4 + h] = ps;
                    g_ad[node * 4 + h] = pd;
                }
            }
        }
    } else {
        #pragma unroll
        for (int mi = 0; mi < 8; mi++) {
            #pragma unroll
            for (int hf = 0; hf < 2; hf++) {
                int r = mi * 16 + g + hf * 8;
                int node = i0 + r;
                if (node >= n) continue;
                #pragma unroll
                for (int ni = 0; ni < 4; ni++) {
                    #pragma unroll
                    for (int j = 0; j < 2; j++) {
                        int cl = ni * 8 + 2 * tig + j;
                        int cid = (wid - 4) * 32 + cl;
                        g_id[(long)node * 128 + cid] = c[mi][ni][hf * 2 + j] + sm[SM_BP + cid];
                    }
                }
            }
        }
    }
}

// ---------------- gather: chunked two-phase softmax aggregate (fp16 values) ----------------
__device__ __forceinline__ float lrelu(float z) { return z > 0.f ? z : 0.2f * z; }

__device__ __forceinline__ float4 ldxw_h(long idx128, int lane) {
    const __half* p = g_xwh + idx128 + lane * 4;
    uint2 u = *(const uint2*)p;
    __half2 h0 = *reinterpret_cast<__half2*>(&u.x);
    __half2 h1 = *reinterpret_cast<__half2*>(&u.y);
    float2 f0 = __half22float2(h0);
    float2 f1 = __half22float2(h1);
    return make_float4(f0.x, f0.y, f1.x, f1.y);
}

__global__ void __launch_bounds__(256) gather_k(const float* __restrict__ bias,
                                                float* __restrict__ out, int n)
{
    __shared__ float4 sq[8][32];
    __shared__ int    ss[8][32];
    int w = threadIdx.x >> 5;
    int lane = threadIdx.x & 31;
    int i = blockIdx.x * 8 + w;
    if (i >= n) return;

    float4 ad  = *(const float4*)&g_ad[i * 4];
    float4 asi = *(const float4*)&g_as[i * 4];
    int beg = g_off[i], end = g_off[i + 1];

    long myb = (long)i * 128;
    float4 xv = ldxw_h(myb, lane);

    float p0 = __expf(lrelu(asi.x + ad.x));
    float p1 = __expf(lrelu(asi.y + ad.y));
    float p2 = __expf(lrelu(asi.z + ad.z));
    float p3 = __expf(lrelu(asi.w + ad.w));
    float d0 = p0, d1 = p1, d2 = p2, d3 = p3;
    float a0 = p0 * xv.x, a1 = p1 * xv.y, a2 = p2 * xv.z, a3 = p3 * xv.w;

    for (int cs = beg; cs < end; cs += 32) {
        int cnt = min(32, end - cs);
        int j = cs + lane;
        if (lane < cnt) {
            int s = __ldg(&g_csr[j]);
            float4 a4 = *(const float4*)&g_as[s * 4];
            float4 q;
            q.x = __expf(lrelu(a4.x + ad.x));
            q.y = __expf(lrelu(a4.y + ad.y));
            q.z = __expf(lrelu(a4.z + ad.z));
            q.w = __expf(lrelu(a4.w + ad.w));
            ss[w][lane] = s;
            sq[w][lane] = q;
        }
        __syncwarp();
        #pragma unroll 4
        for (int t = 0; t < cnt; t++) {
            int st = ss[w][t];
            float4 qt = sq[w][t];
            float4 x4 = ldxw_h((long)st * 128, lane);
            d0 += qt.x; a0 = fmaf(qt.x, x4.x, a0);
            d1 += qt.y; a1 = fmaf(qt.y, x4.y, a1);
            d2 += qt.z; a2 = fmaf(qt.z, x4.z, a2);
            d3 += qt.w; a3 = fmaf(qt.w, x4.w, a3);
        }
        __syncwarp();
    }

    float r0 = a0 / (d0 + 1e-16f);
    float r1 = a1 / (d1 + 1e-16f);
    float r2 = a2 / (d2 + 1e-16f);
    float r3 = a3 / (d3 + 1e-16f);

    long ob = myb + lane;
    out[ob +  0] = fmaxf(g_id[ob +  0] + r0 + __ldg(&bias[lane +  0]), 0.f);
    out[ob + 32] = fmaxf(g_id[ob + 32] + r1 + __ldg(&bias[lane + 32]), 0.f);
    out[ob + 64] = fmaxf(g_id[ob + 64] + r2 + __ldg(&bias[lane + 64]), 0.f);
    out[ob + 96] = fmaxf(g_id[ob + 96] + r3 + __ldg(&bias[lane + 96]), 0.f);
}

// ---------------- launch ----------------
extern "C" void kernel_launch(void* const* d_in, const int* in_sizes, int n_in,
                              void* d_out, int out_size)
{
    const float* x        = (const float*)d_in[0];
    const int*   ei       = (const int*)d_in[1];
    const float* gamma    = (const float*)d_in[2];
    const float* beta     = (const float*)d_in[3];
    const float* Wgat     = (const float*)d_in[4];
    const float* att_src  = (const float*)d_in[5];
    const float* att_dst  = (const float*)d_in[6];
    const float* bias_gat = (const float*)d_in[7];
    const float* Wproj    = (const float*)d_in[8];
    const float* bproj    = (const float*)d_in[9];

    int n = in_sizes[0] / 128;
    int e = in_sizes[1] / 2;
    const int* src = ei;
    const int* dst = ei + e;
    int nb = (n + SCB - 1) / SCB;

    void* curp = nullptr;
    cudaGetSymbolAddress(&curp, g_cur);

    cudaFuncSetAttribute(node_k, cudaFuncAttributeMaxDynamicSharedMemorySize, NODE2_BYTES);

    cudaStream_t s2;
    cudaStreamCreate(&s2);
    cudaEvent_t evFork, evJoin;
    cudaEventCreateWithFlags(&evFork, cudaEventDisableTiming);
    cudaEventCreateWithFlags(&evJoin, cudaEventDisableTiming);

    cudaEventRecord(evFork, 0);
    cudaStreamWaitEvent(s2, evFork, 0);

    // side stream: CSR build
    cudaMemsetAsync(curp, 0, n * sizeof(int), s2);
    hist_k<<<(e + 255) / 256, 256, 0, s2>>>(dst, e);
    bsum_k<<<nb, 256, 0, s2>>>(n);
    bscan_k<<<1, 64, 0, s2>>>(nb);
    scanfin_k<<<nb, 256, 0, s2>>>(n);
    scat_k<<<(e + 255) / 256, 256, 0, s2>>>(src, dst, e);
    cudaEventRecord(evJoin, s2);

    // main stream: GEMM path
    prep2_k<<<256, 128>>>(gamma, beta, Wgat, Wproj);
    node_k<<<(n + TMM - 1) / TMM, 256, NODE2_BYTES>>>(x, att_src, att_dst, bproj, n);

    cudaStreamWaitEvent(0, evJoin, 0);
    gather_k<<<(n + 7) / 8, 256>>>(bias_gat, (float*)d_out, n);

    cudaEventDestroy(evFork);
    cudaEventDestroy(evJoin);
    cudaStreamDestroy(s2);
}

// round 10
// speedup vs baseline: 2.7594x; 1.0818x over previous
#include <cuda_runtime.h>
#include <cuda_bf16.h>
#include <cuda_fp16.h>

// Problem constants (fixed-shape problem)
#define MAXN 50176
#define MAXE 800256

// ---------------- scratch ----------------
__device__ __align__(16) __half g_xwh[MAXN * 128]; // xw per node (fp16), layout [node][cc*4+h]
__device__ __align__(16) __half g_idh[MAXN * 128]; // identity (fp16), layout [node][c]
__device__ __align__(16) float g_as[MAXN * 4];
__device__ __align__(16) float g_ad[MAXN * 4];
__device__ __align__(16) int   g_cur[MAXN];
__device__ int   g_off[MAXN + 1];
__device__ int   g_csr[MAXE];
__device__ int   g_bsum[64];
__device__ float g_G[128];                          // colsum of tf32(gamma*W_gat)
__device__ float g_B[128];                          // beta @ W_gat
__device__ __align__(16) float g_Bp[256 * 128];     // tf32 fused weights TRANSPOSED: [c][k]

// ---------------- tf32 / mma helpers ----------------
__device__ __forceinline__ unsigned tf32u(float x) {
    unsigned r; asm("cvt.rna.tf32.f32 %0, %1;" : "=r"(r) : "f"(x)); return r;
}
__device__ __forceinline__ void mma1688(float* c, const unsigned* a, const unsigned* b) {
    asm volatile("mma.sync.aligned.m16n8k8.row.col.f32.tf32.tf32.f32 "
        "{%0,%1,%2,%3},{%4,%5,%6,%7},{%8,%9},{%0,%1,%2,%3};"
        : "+f"(c[0]), "+f"(c[1]), "+f"(c[2]), "+f"(c[3])
        : "r"(a[0]), "r"(a[1]), "r"(a[2]), "r"(a[3]), "r"(b[0]), "r"(b[1]));
}
__device__ __forceinline__ void cpa16(unsigned s, const float* g) {
    asm volatile("cp.async.ca.shared.global [%0], [%1], 16;" :: "r"(s), "l"(g));
}

// ---------------- prep (merged): tf32 weights transposed + G/B colsums ----------------
__global__ void prep2_k(const float* __restrict__ gamma, const float* __restrict__ beta,
                        const float* __restrict__ Wgat, const float* __restrict__ Wproj) {
    __shared__ float s1[4], s2[4];
    int c = blockIdx.x, k = threadIdx.x;
    int lane = k & 31, wid = k >> 5;
    float w;
    if (c < 128) w = gamma[k] * Wgat[k * 128 + c];
    else         w = Wproj[k * 128 + (c - 128)];
    float wr = __uint_as_float(tf32u(w));
    g_Bp[c * 128 + k] = wr;
    if (c < 128) {
        float sw = wr;
        float sb = beta[k] * Wgat[k * 128 + c];
        #pragma unroll
        for (int o = 16; o > 0; o >>= 1) {
            sw += __shfl_xor_sync(0xFFFFFFFFu, sw, o);
            sb += __shfl_xor_sync(0xFFFFFFFFu, sb, o);
        }
        if (lane == 0) { s1[wid] = sw; s2[wid] = sb; }
        __syncthreads();
        if (k == 0) {
            g_G[c] = s1[0] + s1[1] + s1[2] + s1[3];
            g_B[c] = s2[0] + s2[1] + s2[2] + s2[3];
        }
    }
}

// ---------------- CSR build ----------------
__global__ void hist_k(const int* __restrict__ dst, int e) {
    int i = blockIdx.x * blockDim.x + threadIdx.x;
    if (i < e) atomicAdd(&g_cur[dst[i]], 1);
}

#define SCB 1024
__global__ void bsum_k(int n) {
    __shared__ int wsum[8];
    int b = blockIdx.x, tid = threadIdx.x, lane = tid & 31, wid = tid >> 5;
    int base = b * SCB + tid * 4;
    int4 v = make_int4(0, 0, 0, 0);
    if (base + 3 < n)      v = *(const int4*)&g_cur[base];
    else {
        if (base     < n) v.x = g_cur[base];
        if (base + 1 < n) v.y = g_cur[base + 1];
        if (base + 2 < n) v.z = g_cur[base + 2];
    }
    int s = v.x + v.y + v.z + v.w;
    #pragma unroll
    for (int o = 16; o > 0; o >>= 1) s += __shfl_xor_sync(0xFFFFFFFFu, s, o);
    if (lane == 0) wsum[wid] = s;
    __syncthreads();
    if (wid == 0 && lane < 8) {
        int t = wsum[lane];
        #pragma unroll
        for (int o = 4; o > 0; o >>= 1) t += __shfl_xor_sync(0xFFu, t, o);
        if (lane == 0) g_bsum[b] = t;
    }
}

__global__ void bscan_k(int nb) {
    __shared__ int w0tot;
    int tid = threadIdx.x, lane = tid & 31, wid = tid >> 5;
    int v = (tid < nb) ? g_bsum[tid] : 0;
    int inc = v;
    #pragma unroll
    for (int o = 1; o < 32; o <<= 1) {
        int t = __shfl_up_sync(0xFFFFFFFFu, inc, o);
        if (lane >= o) inc += t;
    }
    if (wid == 0 && lane == 31) w0tot = inc;
    __syncthreads();
    int ex = inc - v + (wid == 1 ? w0tot : 0);
    if (tid < nb) g_bsum[tid] = ex;
}

__global__ void scanfin_k(int n) {
    __shared__ int wsum[8];
    int b = blockIdx.x, tid = threadIdx.x, lane = tid & 31, wid = tid >> 5;
    int base = b * SCB + tid * 4;
    int4 v = make_int4(0, 0, 0, 0);
    if (base + 3 < n)      v = *(const int4*)&g_cur[base];
    else {
        if (base     < n) v.x = g_cur[base];
        if (base + 1 < n) v.y = g_cur[base + 1];
        if (base + 2 < n) v.z = g_cur[base + 2];
    }
    int tsum = v.x + v.y + v.z + v.w;
    int inc = tsum;
    #pragma unroll
    for (int o = 1; o < 32; o <<= 1) {
        int t = __shfl_up_sync(0xFFFFFFFFu, inc, o);
        if (lane >= o) inc += t;
    }
    if (lane == 31) wsum[wid] = inc;
    __syncthreads();
    if (wid == 0 && lane < 8) {
        int wv = wsum[lane];
        int wi = wv;
        #pragma unroll
        for (int o = 1; o < 8; o <<= 1) {
            int t = __shfl_up_sync(0xFFu, wi, o);
            if (lane >= o) wi += t;
        }
        wsum[lane] = wi - wv;
    }
    __syncthreads();
    int e0 = inc - tsum + wsum[wid] + g_bsum[b];
    int e1 = e0 + v.x, e2 = e1 + v.y, e3 = e2 + v.z, e4 = e3 + v.w;
    if (base     < n) { g_cur[base]     = e0; g_off[base + 1] = e1; }
    if (base + 1 < n) { g_cur[base + 1] = e1; g_off[base + 2] = e2; }
    if (base + 2 < n) { g_cur[base + 2] = e2; g_off[base + 3] = e3; }
    if (base + 3 < n) { g_cur[base + 3] = e3; g_off[base + 4] = e4; }
    if (b == 0 && tid == 0) g_off[0] = 0;
}

__global__ void scat_k(const int* __restrict__ src, const int* __restrict__ dst, int e) {
    int i = blockIdx.x * blockDim.x + threadIdx.x;
    if (i < e) {
        int p = atomicAdd(&g_cur[dst[i]], 1);
        g_csr[p] = src[i];
    }
}

// ---------------- node kernel: LN + dual GEMM (tf32, vectorized frags) + attn dots ----
// TMM=64 rows/block -> 108 KB smem -> 2 blocks/SM. k-relabeling as before.
#define TMM 64
#define APITCH 132
#define BKP 36
#define SM_AS 0
#define SM_BF (TMM * APITCH)                 // 8448
#define BKBUF (256 * BKP)                    // 9216
#define SM_MU (SM_BF + 2 * BKBUF)            // 26880
#define SM_RS (SM_MU + TMM)
#define SM_ATT (SM_RS + TMM)
#define SM_G  (SM_ATT + 256)
#define SM_BB (SM_G + 128)
#define SM_BP (SM_BB + 128)
#define NODE2_FLOATS (SM_BP + 128)
#define NODE2_BYTES (NODE2_FLOATS * 4)       // 110592 B

__global__ void __launch_bounds__(256, 2) node_k(
    const float* __restrict__ x, const float* __restrict__ att_src,
    const float* __restrict__ att_dst, const float* __restrict__ bproj, int n)
{
    extern __shared__ float sm[];
    int tid = threadIdx.x;
    int wid = tid >> 5, lane = tid & 31;
    int g = lane >> 2, tig = lane & 3;
    int i0 = blockIdx.x * TMM;
    unsigned smbase = (unsigned)__cvta_generic_to_shared(sm);

    if (tid < 128) {
        sm[SM_ATT + tid]       = att_src[tid];
        sm[SM_ATT + 128 + tid] = att_dst[tid];
        sm[SM_G + tid]  = g_G[tid];
        sm[SM_BB + tid] = g_B[tid];
        sm[SM_BP + tid] = bproj[tid];
    }

    // B chunk loader: chunk kc -> Bs[c*BKP .. +31]
    auto loadB = [&](int kc, int buf) {
        const float* gp = g_Bp + kc * 32;
        unsigned bs = smbase + (SM_BF + buf * BKBUF) * 4;
        #pragma unroll
        for (int u = 0; u < 8; u++) {
            int idx = u * 256 + tid;
            int c = idx >> 3, q = idx & 7;
            cpa16(bs + (c * BKP + q * 4) * 4, gp + c * 128 + q * 4);
        }
        asm volatile("cp.async.commit_group;");
    };
    loadB(0, 0);

    // A fill (row-major tf32) + LayerNorm stats
    for (int rr = 0; rr < TMM / 8; rr++) {
        int r = wid * (TMM / 8) + rr;
        int node = i0 + r;
        float4 v = make_float4(0.f, 0.f, 0.f, 0.f);
        if (node < n) v = *(const float4*)&x[(long)node * 128 + lane * 4];
        float s = v.x + v.y + v.z + v.w;
        float q = v.x * v.x + v.y * v.y + v.z * v.z + v.w * v.w;
        #pragma unroll
        for (int o = 16; o > 0; o >>= 1) {
            s += __shfl_xor_sync(0xFFFFFFFFu, s, o);
            q += __shfl_xor_sync(0xFFFFFFFFu, q, o);
        }
        float mu = s * (1.f / 128.f);
        float var = q * (1.f / 128.f) - mu * mu;
        if (lane == 0) { sm[SM_MU + r] = mu; sm[SM_RS + r] = rsqrtf(var + 1e-5f); }
        float4 t;
        t.x = __uint_as_float(tf32u(v.x));
        t.y = __uint_as_float(tf32u(v.y));
        t.z = __uint_as_float(tf32u(v.z));
        t.w = __uint_as_float(tf32u(v.w));
        *(float4*)&sm[SM_AS + r * APITCH + lane * 4] = t;
    }

    float c[4][4][4];
    #pragma unroll
    for (int a = 0; a < 4; a++)
        #pragma unroll
        for (int b = 0; b < 4; b++)
            #pragma unroll
            for (int d = 0; d < 4; d++) c[a][b][d] = 0.f;

    int colb = wid * 32;

    for (int kc = 0; kc < 4; kc++) {
        if (kc) __syncthreads();
        if (kc < 3) loadB(kc + 1, (kc + 1) & 1);
        if (kc < 3) asm volatile("cp.async.wait_group 1;");
        else        asm volatile("cp.async.wait_group 0;");
        __syncthreads();

        const float* Bh = &sm[SM_BF + (kc & 1) * BKBUF];

        float4 bf[4][2];
        #pragma unroll
        for (int ni = 0; ni < 4; ni++) {
            int col = colb + ni * 8 + g;
            const float* bp = &Bh[col * BKP + tig * 8];
            bf[ni][0] = *(const float4*)bp;
            bf[ni][1] = *(const float4*)(bp + 4);
        }

        #pragma unroll
        for (int mi = 0; mi < 4; mi++) {
            const float* Ar = &sm[SM_AS + (mi * 16 + g) * APITCH + kc * 32 + tig * 8];
            const float* Ar8 = Ar + 8 * APITCH;
            float4 a0 = *(const float4*)Ar;
            float4 a1 = *(const float4*)(Ar + 4);
            float4 e0 = *(const float4*)Ar8;
            float4 e1 = *(const float4*)(Ar8 + 4);
            unsigned a[4]; unsigned b[2];
            a[0] = __float_as_uint(a0.x); a[1] = __float_as_uint(e0.x);
            a[2] = __float_as_uint(a0.y); a[3] = __float_as_uint(e0.y);
            #pragma unroll
            for (int ni = 0; ni < 4; ni++) {
                b[0] = __float_as_uint(bf[ni][0].x); b[1] = __float_as_uint(bf[ni][0].y);
                mma1688(c[mi][ni], a, b);
            }
            a[0] = __float_as_uint(a0.z); a[1] = __float_as_uint(e0.z);
            a[2] = __float_as_uint(a0.w); a[3] = __float_as_uint(e0.w);
            #pragma unroll
            for (int ni = 0; ni < 4; ni++) {
                b[0] = __float_as_uint(bf[ni][0].z); b[1] = __float_as_uint(bf[ni][0].w);
                mma1688(c[mi][ni], a, b);
            }
            a[0] = __float_as_uint(a1.x); a[1] = __float_as_uint(e1.x);
            a[2] = __float_as_uint(a1.y); a[3] = __float_as_uint(e1.y);
            #pragma unroll
            for (int ni = 0; ni < 4; ni++) {
                b[0] = __float_as_uint(bf[ni][1].x); b[1] = __float_as_uint(bf[ni][1].y);
                mma1688(c[mi][ni], a, b);
            }
            a[0] = __float_as_uint(a1.z); a[1] = __float_as_uint(e1.z);
            a[2] = __float_as_uint(a1.w); a[3] = __float_as_uint(e1.w);
            #pragma unroll
            for (int ni = 0; ni < 4; ni++) {
                b[0] = __float_as_uint(bf[ni][1].z); b[1] = __float_as_uint(bf[ni][1].w);
                mma1688(c[mi][ni], a, b);
            }
        }
    }

    // Epilogue
    if (wid < 4) {
        int h = wid;
        #pragma unroll
        for (int mi = 0; mi < 4; mi++) {
            #pragma unroll
            for (int hf = 0; hf < 2; hf++) {
                int r = mi * 16 + g + hf * 8;
                int node = i0 + r;
                float mu = sm[SM_MU + r], rs = sm[SM_RS + r];
                float ps = 0.f, pd = 0.f;
                #pragma unroll
                for (int ni = 0; ni < 4; ni++) {
                    #pragma unroll
                    for (int j = 0; j < 2; j++) {
                        int cl = ni * 8 + 2 * tig + j;
                        int cg = colb + cl;
                        float acc = c[mi][ni][hf * 2 + j];
                        float val = rs * (acc - mu * sm[SM_G + cg]) + sm[SM_BB + cg];
                        ps += val * sm[SM_ATT + cg];
                        pd += val * sm[SM_ATT + 128 + cg];
                        if (node < n)
                            g_xwh[(long)node * 128 + cl * 4 + h] = __float2half_rn(val);
                    }
                }
                ps += __shfl_xor_sync(0xFFFFFFFFu, ps, 1);
                ps += __shfl_xor_sync(0xFFFFFFFFu, ps, 2);
                pd += __shfl_xor_sync(0xFFFFFFFFu, pd, 1);
                pd += __shfl_xor_sync(0xFFFFFFFFu, pd, 2);
                if (tig == 0 && node < n) {
                    g_as[node * 4 + h] = ps;
                    g_ad[node * 4 + h] = pd;
                }
            }
        }
    } else {
        #pragma unroll
        for (int mi = 0; mi < 4; mi++) {
            #pragma unroll
            for (int hf = 0; hf < 2; hf++) {
                int r = mi * 16 + g + hf * 8;
                int node = i0 + r;
                if (node >= n) continue;
                #pragma unroll
                for (int ni = 0; ni < 4; ni++) {
                    int cid0 = (wid - 4) * 32 + ni * 8 + 2 * tig;
                    float v0 = c[mi][ni][hf * 2 + 0] + sm[SM_BP + cid0];
                    float v1 = c[mi][ni][hf * 2 + 1] + sm[SM_BP + cid0 + 1];
                    *(__half2*)&g_idh[(long)node * 128 + cid0] = __floats2half2_rn(v0, v1);
                }
            }
        }
    }
}

// ---------------- gather: chunked two-phase softmax aggregate (fp16 values) ----------------
__device__ __forceinline__ float lrelu(float z) { return z > 0.f ? z : 0.2f * z; }

__device__ __forceinline__ float4 ldxw_h(long idx128, int lane) {
    const __half* p = g_xwh + idx128 + lane * 4;
    uint2 u = *(const uint2*)p;
    __half2 h0 = *reinterpret_cast<__half2*>(&u.x);
    __half2 h1 = *reinterpret_cast<__half2*>(&u.y);
    float2 f0 = __half22float2(h0);
    float2 f1 = __half22float2(h1);
    return make_float4(f0.x, f0.y, f1.x, f1.y);
}

__global__ void __launch_bounds__(256) gather_k(const float* __restrict__ bias,
                                                float* __restrict__ out, int n)
{
    __shared__ float4 sq[8][32];
    __shared__ int    ss[8][32];
    int w = threadIdx.x >> 5;
    int lane = threadIdx.x & 31;
    int i = blockIdx.x * 8 + w;
    if (i >= n) return;

    float4 ad  = *(const float4*)&g_ad[i * 4];
    float4 asi = *(const float4*)&g_as[i * 4];
    int beg = g_off[i], end = g_off[i + 1];

    long myb = (long)i * 128;
    float4 xv = ldxw_h(myb, lane);

    float p0 = __expf(lrelu(asi.x + ad.x));
    float p1 = __expf(lrelu(asi.y + ad.y));
    float p2 = __expf(lrelu(asi.z + ad.z));
    float p3 = __expf(lrelu(asi.w + ad.w));
    float d0 = p0, d1 = p1, d2 = p2, d3 = p3;
    float a0 = p0 * xv.x, a1 = p1 * xv.y, a2 = p2 * xv.z, a3 = p3 * xv.w;

    for (int cs = beg; cs < end; cs += 32) {
        int cnt = min(32, end - cs);
        int j = cs + lane;
        if (lane < cnt) {
            int s = __ldg(&g_csr[j]);
            float4 a4 = *(const float4*)&g_as[s * 4];
            float4 q;
            q.x = __expf(lrelu(a4.x + ad.x));
            q.y = __expf(lrelu(a4.y + ad.y));
            q.z = __expf(lrelu(a4.z + ad.z));
            q.w = __expf(lrelu(a4.w + ad.w));
            ss[w][lane] = s;
            sq[w][lane] = q;
        }
        __syncwarp();
        #pragma unroll 4
        for (int t = 0; t < cnt; t++) {
            int st = ss[w][t];
            float4 qt = sq[w][t];
            float4 x4 = ldxw_h((long)st * 128, lane);
            d0 += qt.x; a0 = fmaf(qt.x, x4.x, a0);
            d1 += qt.y; a1 = fmaf(qt.y, x4.y, a1);
            d2 += qt.z; a2 = fmaf(qt.z, x4.z, a2);
            d3 += qt.w; a3 = fmaf(qt.w, x4.w, a3);
        }
        __syncwarp();
    }

    float r0 = a0 / (d0 + 1e-16f);
    float r1 = a1 / (d1 + 1e-16f);
    float r2 = a2 / (d2 + 1e-16f);
    float r3 = a3 / (d3 + 1e-16f);

    long ob = myb + lane;
    out[ob +  0] = fmaxf(__half2float(g_idh[ob +  0]) + r0 + __ldg(&bias[lane +  0]), 0.f);
    out[ob + 32] = fmaxf(__half2float(g_idh[ob + 32]) + r1 + __ldg(&bias[lane + 32]), 0.f);
    out[ob + 64] = fmaxf(__half2float(g_idh[ob + 64]) + r2 + __ldg(&bias[lane + 64]), 0.f);
    out[ob + 96] = fmaxf(__half2float(g_idh[ob + 96]) + r3 + __ldg(&bias[lane + 96]), 0.f);
}

// ---------------- launch ----------------
extern "C" void kernel_launch(void* const* d_in, const int* in_sizes, int n_in,
                              void* d_out, int out_size)
{
    const float* x        = (const float*)d_in[0];
    const int*   ei       = (const int*)d_in[1];
    const float* gamma    = (const float*)d_in[2];
    const float* beta     = (const float*)d_in[3];
    const float* Wgat     = (const float*)d_in[4];
    const float* att_src  = (const float*)d_in[5];
    const float* att_dst  = (const float*)d_in[6];
    const float* bias_gat = (const float*)d_in[7];
    const float* Wproj    = (const float*)d_in[8];
    const float* bproj    = (const float*)d_in[9];

    int n = in_sizes[0] / 128;
    int e = in_sizes[1] / 2;
    const int* src = ei;
    const int* dst = ei + e;
    int nb = (n + SCB - 1) / SCB;

    void* curp = nullptr;
    cudaGetSymbolAddress(&curp, g_cur);

    cudaFuncSetAttribute(node_k, cudaFuncAttributeMaxDynamicSharedMemorySize, NODE2_BYTES);

    cudaStream_t s2;
    cudaStreamCreate(&s2);
    cudaEvent_t evFork, evJoin;
    cudaEventCreateWithFlags(&evFork, cudaEventDisableTiming);
    cudaEventCreateWithFlags(&evJoin, cudaEventDisableTiming);

    cudaEventRecord(evFork, 0);
    cudaStreamWaitEvent(s2, evFork, 0);

    // side stream: CSR build
    cudaMemsetAsync(curp, 0, n * sizeof(int), s2);
    hist_k<<<(e + 255) / 256, 256, 0, s2>>>(dst, e);
    bsum_k<<<nb, 256, 0, s2>>>(n);
    bscan_k<<<1, 64, 0, s2>>>(nb);
    scanfin_k<<<nb, 256, 0, s2>>>(n);
    scat_k<<<(e + 255) / 256, 256, 0, s2>>>(src, dst, e);
    cudaEventRecord(evJoin, s2);

    // main stream: GEMM path
    prep2_k<<<256, 128>>>(gamma, beta, Wgat, Wproj);
    node_k<<<(n + TMM - 1) / TMM, 256, NODE2_BYTES>>>(x, att_src, att_dst, bproj, n);

    cudaStreamWaitEvent(0, evJoin, 0);
    gather_k<<<(n + 7) / 8, 256>>>(bias_gat, (float*)d_out, n);

    cudaEventDestroy(evFork);
    cudaEventDestroy(evJoin);
    cudaStreamDestroy(s2);
}

// round 11
// speedup vs baseline: 2.7645x; 1.0018x over previous
#include <cuda_runtime.h>
#include <cuda_bf16.h>
#include <cuda_fp16.h>

// Problem constants (fixed-shape problem)
#define MAXN 50176
#define MAXE 800256

// ---------------- scratch ----------------
__device__ __align__(16) __half g_xwh[MAXN * 128]; // xw per node (fp16), layout [node][cc*4+h]
__device__ __align__(16) __half g_idh[MAXN * 128]; // identity (fp16), layout [node][c]
__device__ __align__(16) float g_as[MAXN * 4];
__device__ __align__(16) float g_ad[MAXN * 4];
__device__ __align__(16) int   g_cur[MAXN];
__device__ int   g_off[MAXN + 1];
__device__ int   g_csr[MAXE];
__device__ volatile unsigned long long g_spack[64]; // packed (flag<<32 | aggregate)
__device__ float g_G[128];                          // colsum of tf32(gamma*W_gat)
__device__ float g_B[128];                          // beta @ W_gat
__device__ __align__(16) float g_Bp[256 * 128];     // tf32 fused weights TRANSPOSED: [c][k]

// ---------------- tf32 / mma helpers ----------------
__device__ __forceinline__ unsigned tf32u(float x) {
    unsigned r; asm("cvt.rna.tf32.f32 %0, %1;" : "=r"(r) : "f"(x)); return r;
}
__device__ __forceinline__ void mma1688(float* c, const unsigned* a, const unsigned* b) {
    asm volatile("mma.sync.aligned.m16n8k8.row.col.f32.tf32.tf32.f32 "
        "{%0,%1,%2,%3},{%4,%5,%6,%7},{%8,%9},{%0,%1,%2,%3};"
        : "+f"(c[0]), "+f"(c[1]), "+f"(c[2]), "+f"(c[3])
        : "r"(a[0]), "r"(a[1]), "r"(a[2]), "r"(a[3]), "r"(b[0]), "r"(b[1]));
}
__device__ __forceinline__ void cpa16(unsigned s, const float* g) {
    asm volatile("cp.async.ca.shared.global [%0], [%1], 16;" :: "r"(s), "l"(g));
}

// ---------------- prep (merged): tf32 weights transposed + G/B colsums ----------------
__global__ void prep2_k(const float* __restrict__ gamma, const float* __restrict__ beta,
                        const float* __restrict__ Wgat, const float* __restrict__ Wproj) {
    __shared__ float s1[4], s2[4];
    int c = blockIdx.x, k = threadIdx.x;
    int lane = k & 31, wid = k >> 5;
    float w;
    if (c < 128) w = gamma[k] * Wgat[k * 128 + c];
    else         w = Wproj[k * 128 + (c - 128)];
    float wr = __uint_as_float(tf32u(w));
    g_Bp[c * 128 + k] = wr;
    if (c < 128) {
        float sw = wr;
        float sb = beta[k] * Wgat[k * 128 + c];
        #pragma unroll
        for (int o = 16; o > 0; o >>= 1) {
            sw += __shfl_xor_sync(0xFFFFFFFFu, sw, o);
            sb += __shfl_xor_sync(0xFFFFFFFFu, sb, o);
        }
        if (lane == 0) { s1[wid] = sw; s2[wid] = sb; }
        __syncthreads();
        if (k == 0) {
            g_G[c] = s1[0] + s1[1] + s1[2] + s1[3];
            g_B[c] = s2[0] + s2[1] + s2[2] + s2[3];
        }
    }
}

// ---------------- CSR build ----------------
__global__ void hist_k(const int* __restrict__ dst, int e) {
    // re-zero the scan publish words each replay (hist always precedes scan1_k)
    if (blockIdx.x == 0 && threadIdx.x < 64) g_spack[threadIdx.x] = 0ull;
    int i = blockIdx.x * blockDim.x + threadIdx.x;
    if (i < e) atomicAdd(&g_cur[dst[i]], 1);
}

// Single-pass scan with decoupled lookback. grid = nb (<=49), block = 256.
// Publishes (1<<32 | aggregate) as one 64-bit word -> flag+value read atomically.
// Publish happens before any wait => deadlock-free under any block scheduling.
#define SCB 1024
__global__ void scan1_k(int n) {
    __shared__ int wsum[8];
    __shared__ int s_off;
    int b = blockIdx.x, tid = threadIdx.x, lane = tid & 31, wid = tid >> 5;
    int base = b * SCB + tid * 4;
    int4 v = make_int4(0, 0, 0, 0);
    if (base + 3 < n)      v = *(const int4*)&g_cur[base];
    else {
        if (base     < n) v.x = g_cur[base];
        if (base + 1 < n) v.y = g_cur[base + 1];
        if (base + 2 < n) v.z = g_cur[base + 2];
    }
    int tsum = v.x + v.y + v.z + v.w;
    int inc = tsum;
    #pragma unroll
    for (int o = 1; o < 32; o <<= 1) {
        int t = __shfl_up_sync(0xFFFFFFFFu, inc, o);
        if (lane >= o) inc += t;
    }
    if (lane == 31) wsum[wid] = inc;
    __syncthreads();

    // publish aggregate (warp 0 lane 0), BEFORE any waiting
    if (tid == 0) {
        int tot = wsum[0] + wsum[1] + wsum[2] + wsum[3]
                + wsum[4] + wsum[5] + wsum[6] + wsum[7];
        g_spack[b] = (1ull << 32) | (unsigned)tot;
    }
    // warp 0: convert wsum to exclusive warp offsets
    if (wid == 0 && lane < 8) {
        int wv = wsum[lane];
        int wi = wv;
        #pragma unroll
        for (int o = 1; o < 8; o <<= 1) {
            int t = __shfl_up_sync(0xFFu, wi, o);
            if (lane >= o) wi += t;
        }
        wsum[lane] = wi - wv;
    }
    // warp 1: lookback over all predecessors (lane-parallel poll + sum)
    if (wid == 1) {
        int acc = 0;
        for (int p = lane; p < b; p += 32) {
            unsigned long long pk;
            do { pk = g_spack[p]; } while (pk == 0ull);
            acc += (int)(unsigned)pk;
        }
        #pragma unroll
        for (int o = 16; o > 0; o >>= 1) acc += __shfl_xor_sync(0xFFFFFFFFu, acc, o);
        if (lane == 0) s_off = acc;
    }
    __syncthreads();

    int e0 = inc - tsum + wsum[wid] + s_off;
    int e1 = e0 + v.x, e2 = e1 + v.y, e3 = e2 + v.z, e4 = e3 + v.w;
    if (base     < n) { g_cur[base]     = e0; g_off[base + 1] = e1; }
    if (base + 1 < n) { g_cur[base + 1] = e1; g_off[base + 2] = e2; }
    if (base + 2 < n) { g_cur[base + 2] = e2; g_off[base + 3] = e3; }
    if (base + 3 < n) { g_cur[base + 3] = e3; g_off[base + 4] = e4; }
    if (b == 0 && tid == 0) g_off[0] = 0;
}

__global__ void scat_k(const int* __restrict__ src, const int* __restrict__ dst, int e) {
    int i = blockIdx.x * blockDim.x + threadIdx.x;
    if (i < e) {
        int p = atomicAdd(&g_cur[dst[i]], 1);
        g_csr[p] = src[i];
    }
}

// ---------------- node kernel: LN + dual GEMM (tf32, vectorized frags) + attn dots ----
// TMM=64 rows/block -> 108 KB smem -> 2 blocks/SM. k-relabeling as before.
#define TMM 64
#define APITCH 132
#define BKP 36
#define SM_AS 0
#define SM_BF (TMM * APITCH)                 // 8448
#define BKBUF (256 * BKP)                    // 9216
#define SM_MU (SM_BF + 2 * BKBUF)            // 26880
#define SM_RS (SM_MU + TMM)
#define SM_ATT (SM_RS + TMM)
#define SM_G  (SM_ATT + 256)
#define SM_BB (SM_G + 128)
#define SM_BP (SM_BB + 128)
#define NODE2_FLOATS (SM_BP + 128)
#define NODE2_BYTES (NODE2_FLOATS * 4)       // 110592 B

__global__ void __launch_bounds__(256, 2) node_k(
    const float* __restrict__ x, const float* __restrict__ att_src,
    const float* __restrict__ att_dst, const float* __restrict__ bproj, int n)
{
    extern __shared__ float sm[];
    int tid = threadIdx.x;
    int wid = tid >> 5, lane = tid & 31;
    int g = lane >> 2, tig = lane & 3;
    int i0 = blockIdx.x * TMM;
    unsigned smbase = (unsigned)__cvta_generic_to_shared(sm);

    if (tid < 128) {
        sm[SM_ATT + tid]       = att_src[tid];
        sm[SM_ATT + 128 + tid] = att_dst[tid];
        sm[SM_G + tid]  = g_G[tid];
        sm[SM_BB + tid] = g_B[tid];
        sm[SM_BP + tid] = bproj[tid];
    }

    // B chunk loader: chunk kc -> Bs[c*BKP .. +31]
    auto loadB = [&](int kc, int buf) {
        const float* gp = g_Bp + kc * 32;
        unsigned bs = smbase + (SM_BF + buf * BKBUF) * 4;
        #pragma unroll
        for (int u = 0; u < 8; u++) {
            int idx = u * 256 + tid;
            int c = idx >> 3, q = idx & 7;
            cpa16(bs + (c * BKP + q * 4) * 4, gp + c * 128 + q * 4);
        }
        asm volatile("cp.async.commit_group;");
    };
    loadB(0, 0);

    // A fill (row-major tf32) + LayerNorm stats
    for (int rr = 0; rr < TMM / 8; rr++) {
        int r = wid * (TMM / 8) + rr;
        int node = i0 + r;
        float4 v = make_float4(0.f, 0.f, 0.f, 0.f);
        if (node < n) v = *(const float4*)&x[(long)node * 128 + lane * 4];
        float s = v.x + v.y + v.z + v.w;
        float q = v.x * v.x + v.y * v.y + v.z * v.z + v.w * v.w;
        #pragma unroll
        for (int o = 16; o > 0; o >>= 1) {
            s += __shfl_xor_sync(0xFFFFFFFFu, s, o);
            q += __shfl_xor_sync(0xFFFFFFFFu, q, o);
        }
        float mu = s * (1.f / 128.f);
        float var = q * (1.f / 128.f) - mu * mu;
        if (lane == 0) { sm[SM_MU + r] = mu; sm[SM_RS + r] = rsqrtf(var + 1e-5f); }
        float4 t;
        t.x = __uint_as_float(tf32u(v.x));
        t.y = __uint_as_float(tf32u(v.y));
        t.z = __uint_as_float(tf32u(v.z));
        t.w = __uint_as_float(tf32u(v.w));
        *(float4*)&sm[SM_AS + r * APITCH + lane * 4] = t;
    }

    float c[4][4][4];
    #pragma unroll
    for (int a = 0; a < 4; a++)
        #pragma unroll
        for (int b = 0; b < 4; b++)
            #pragma unroll
            for (int d = 0; d < 4; d++) c[a][b][d] = 0.f;

    int colb = wid * 32;

    for (int kc = 0; kc < 4; kc++) {
        if (kc) __syncthreads();
        if (kc < 3) loadB(kc + 1, (kc + 1) & 1);
        if (kc < 3) asm volatile("cp.async.wait_group 1;");
        else        asm volatile("cp.async.wait_group 0;");
        __syncthreads();

        const float* Bh = &sm[SM_BF + (kc & 1) * BKBUF];

        float4 bf[4][2];
        #pragma unroll
        for (int ni = 0; ni < 4; ni++) {
            int col = colb + ni * 8 + g;
            const float* bp = &Bh[col * BKP + tig * 8];
            bf[ni][0] = *(const float4*)bp;
            bf[ni][1] = *(const float4*)(bp + 4);
        }

        #pragma unroll
        for (int mi = 0; mi < 4; mi++) {
            const float* Ar = &sm[SM_AS + (mi * 16 + g) * APITCH + kc * 32 + tig * 8];
            const float* Ar8 = Ar + 8 * APITCH;
            float4 a0 = *(const float4*)Ar;
            float4 a1 = *(const float4*)(Ar + 4);
            float4 e0 = *(const float4*)Ar8;
            float4 e1 = *(const float4*)(Ar8 + 4);
            unsigned a[4]; unsigned b[2];
            a[0] = __float_as_uint(a0.x); a[1] = __float_as_uint(e0.x);
            a[2] = __float_as_uint(a0.y); a[3] = __float_as_uint(e0.y);
            #pragma unroll
            for (int ni = 0; ni < 4; ni++) {
                b[0] = __float_as_uint(bf[ni][0].x); b[1] = __float_as_uint(bf[ni][0].y);
                mma1688(c[mi][ni], a, b);
            }
            a[0] = __float_as_uint(a0.z); a[1] = __float_as_uint(e0.z);
            a[2] = __float_as_uint(a0.w); a[3] = __float_as_uint(e0.w);
            #pragma unroll
            for (int ni = 0; ni < 4; ni++) {
                b[0] = __float_as_uint(bf[ni][0].z); b[1] = __float_as_uint(bf[ni][0].w);
                mma1688(c[mi][ni], a, b);
            }
            a[0] = __float_as_uint(a1.x); a[1] = __float_as_uint(e1.x);
            a[2] = __float_as_uint(a1.y); a[3] = __float_as_uint(e1.y);
            #pragma unroll
            for (int ni = 0; ni < 4; ni++) {
                b[0] = __float_as_uint(bf[ni][1].x); b[1] = __float_as_uint(bf[ni][1].y);
                mma1688(c[mi][ni], a, b);
            }
            a[0] = __float_as_uint(a1.z); a[1] = __float_as_uint(e1.z);
            a[2] = __float_as_uint(a1.w); a[3] = __float_as_uint(e1.w);
            #pragma unroll
            for (int ni = 0; ni < 4; ni++) {
                b[0] = __float_as_uint(bf[ni][1].z); b[1] = __float_as_uint(bf[ni][1].w);
                mma1688(c[mi][ni], a, b);
            }
        }
    }

    // Epilogue
    if (wid < 4) {
        int h = wid;
        #pragma unroll
        for (int mi = 0; mi < 4; mi++) {
            #pragma unroll
            for (int hf = 0; hf < 2; hf++) {
                int r = mi * 16 + g + hf * 8;
                int node = i0 + r;
                float mu = sm[SM_MU + r], rs = sm[SM_RS + r];
                float ps = 0.f, pd = 0.f;
                #pragma unroll
                for (int ni = 0; ni < 4; ni++) {
                    #pragma unroll
                    for (int j = 0; j < 2; j++) {
                        int cl = ni * 8 + 2 * tig + j;
                        int cg = colb + cl;
                        float acc = c[mi][ni][hf * 2 + j];
                        float val = rs * (acc - mu * sm[SM_G + cg]) + sm[SM_BB + cg];
                        ps += val * sm[SM_ATT + cg];
                        pd += val * sm[SM_ATT + 128 + cg];
                        if (node < n)
                            g_xwh[(long)node * 128 + cl * 4 + h] = __float2half_rn(val);
                    }
                }
                ps += __shfl_xor_sync(0xFFFFFFFFu, ps, 1);
                ps += __shfl_xor_sync(0xFFFFFFFFu, ps, 2);
                pd += __shfl_xor_sync(0xFFFFFFFFu, pd, 1);
                pd += __shfl_xor_sync(0xFFFFFFFFu, pd, 2);
                if (tig == 0 && node < n) {
                    g_as[node * 4 + h] = ps;
                    g_ad[node * 4 + h] = pd;
                }
            }
        }
    } else {
        #pragma unroll
        for (int mi = 0; mi < 4; mi++) {
            #pragma unroll
            for (int hf = 0; hf < 2; hf++) {
                int r = mi * 16 + g + hf * 8;
                int node = i0 + r;
                if (node >= n) continue;
                #pragma unroll
                for (int ni = 0; ni < 4; ni++) {
                    int cid0 = (wid - 4) * 32 + ni * 8 + 2 * tig;
                    float v0 = c[mi][ni][hf * 2 + 0] + sm[SM_BP + cid0];
                    float v1 = c[mi][ni][hf * 2 + 1] + sm[SM_BP + cid0 + 1];
                    *(__half2*)&g_idh[(long)node * 128 + cid0] = __floats2half2_rn(v0, v1);
                }
            }
        }
    }
}

// ---------------- gather: chunked two-phase softmax aggregate (fp16 values) ----------------
__device__ __forceinline__ float lrelu(float z) { return z > 0.f ? z : 0.2f * z; }

__device__ __forceinline__ float4 ldxw_h(long idx128, int lane) {
    const __half* p = g_xwh + idx128 + lane * 4;
    uint2 u = *(const uint2*)p;
    __half2 h0 = *reinterpret_cast<__half2*>(&u.x);
    __half2 h1 = *reinterpret_cast<__half2*>(&u.y);
    float2 f0 = __half22float2(h0);
    float2 f1 = __half22float2(h1);
    return make_float4(f0.x, f0.y, f1.x, f1.y);
}

__global__ void __launch_bounds__(256) gather_k(const float* __restrict__ bias,
                                                float* __restrict__ out, int n)
{
    __shared__ float4 sq[8][32];
    __shared__ int    ss[8][32];
    int w = threadIdx.x >> 5;
    int lane = threadIdx.x & 31;
    int i = blockIdx.x * 8 + w;
    if (i >= n) return;

    float4 ad  = *(const float4*)&g_ad[i * 4];
    float4 asi = *(const float4*)&g_as[i * 4];
    int beg = g_off[i], end = g_off[i + 1];

    long myb = (long)i * 128;
    float4 xv = ldxw_h(myb, lane);

    float p0 = __expf(lrelu(asi.x + ad.x));
    float p1 = __expf(lrelu(asi.y + ad.y));
    float p2 = __expf(lrelu(asi.z + ad.z));
    float p3 = __expf(lrelu(asi.w + ad.w));
    float d0 = p0, d1 = p1, d2 = p2, d3 = p3;
    float a0 = p0 * xv.x, a1 = p1 * xv.y, a2 = p2 * xv.z, a3 = p3 * xv.w;

    for (int cs = beg; cs < end; cs += 32) {
        int cnt = min(32, end - cs);
        int j = cs + lane;
        if (lane < cnt) {
            int s = __ldg(&g_csr[j]);
            float4 a4 = *(const float4*)&g_as[s * 4];
            float4 q;
            q.x = __expf(lrelu(a4.x + ad.x));
            q.y = __expf(lrelu(a4.y + ad.y));
            q.z = __expf(lrelu(a4.z + ad.z));
            q.w = __expf(lrelu(a4.w + ad.w));
            ss[w][lane] = s;
            sq[w][lane] = q;
        }
        __syncwarp();
        #pragma unroll 4
        for (int t = 0; t < cnt; t++) {
            int st = ss[w][t];
            float4 qt = sq[w][t];
            float4 x4 = ldxw_h((long)st * 128, lane);
            d0 += qt.x; a0 = fmaf(qt.x, x4.x, a0);
            d1 += qt.y; a1 = fmaf(qt.y, x4.y, a1);
            d2 += qt.z; a2 = fmaf(qt.z, x4.z, a2);
            d3 += qt.w; a3 = fmaf(qt.w, x4.w, a3);
        }
        __syncwarp();
    }

    float r0 = a0 / (d0 + 1e-16f);
    float r1 = a1 / (d1 + 1e-16f);
    float r2 = a2 / (d2 + 1e-16f);
    float r3 = a3 / (d3 + 1e-16f);

    long ob = myb + lane;
    out[ob +  0] = fmaxf(__half2float(g_idh[ob +  0]) + r0 + __ldg(&bias[lane +  0]), 0.f);
    out[ob + 32] = fmaxf(__half2float(g_idh[ob + 32]) + r1 + __ldg(&bias[lane + 32]), 0.f);
    out[ob + 64] = fmaxf(__half2float(g_idh[ob + 64]) + r2 + __ldg(&bias[lane + 64]), 0.f);
    out[ob + 96] = fmaxf(__half2float(g_idh[ob + 96]) + r3 + __ldg(&bias[lane + 96]), 0.f);
}

// ---------------- launch ----------------
extern "C" void kernel_launch(void* const* d_in, const int* in_sizes, int n_in,
                              void* d_out, int out_size)
{
    const float* x        = (const float*)d_in[0];
    const int*   ei       = (const int*)d_in[1];
    const float* gamma    = (const float*)d_in[2];
    const float* beta     = (const float*)d_in[3];
    const float* Wgat     = (const float*)d_in[4];
    const float* att_src  = (const float*)d_in[5];
    const float* att_dst  = (const float*)d_in[6];
    const float* bias_gat = (const float*)d_in[7];
    const float* Wproj    = (const float*)d_in[8];
    const float* bproj    = (const float*)d_in[9];

    int n = in_sizes[0] / 128;
    int e = in_sizes[1] / 2;
    const int* src = ei;
    const int* dst = ei + e;
    int nb = (n + SCB - 1) / SCB;

    void* curp = nullptr;
    cudaGetSymbolAddress(&curp, g_cur);

    cudaFuncSetAttribute(node_k, cudaFuncAttributeMaxDynamicSharedMemorySize, NODE2_BYTES);

    cudaStream_t s2;
    cudaStreamCreate(&s2);
    cudaEvent_t evFork, evJoin;
    cudaEventCreateWithFlags(&evFork, cudaEventDisableTiming);
    cudaEventCreateWithFlags(&evJoin, cudaEventDisableTiming);

    cudaEventRecord(evFork, 0);
    cudaStreamWaitEvent(s2, evFork, 0);

    // side stream: CSR build (memset -> hist -> single-pass scan -> scat)
    cudaMemsetAsync(curp, 0, n * sizeof(int), s2);
    hist_k<<<(e + 255) / 256, 256, 0, s2>>>(dst, e);
    scan1_k<<<nb, 256, 0, s2>>>(n);
    scat_k<<<(e + 255) / 256, 256, 0, s2>>>(src, dst, e);
    cudaEventRecord(evJoin, s2);

    // main stream: GEMM path
    prep2_k<<<256, 128>>>(gamma, beta, Wgat, Wproj);
    node_k<<<(n + TMM - 1) / TMM, 256, NODE2_BYTES>>>(x, att_src, att_dst, bproj, n);

    cudaStreamWaitEvent(0, evJoin, 0);
    gather_k<<<(n + 7) / 8, 256>>>(bias_gat, (float*)d_out, n);

    cudaEventDestroy(evFork);
    cudaEventDestroy(evJoin);
    cudaStreamDestroy(s2);
}